// round 5
// baseline (speedup 1.0000x reference)
#include <cuda_runtime.h>
#include <math.h>

#define BB 64
#define TT 128
#define DD 512
#define NBD (BB*DD)        /* 32768 */
#define BTD (BB*TT*DD)     /* 4194304 */
#define G_CTAS 128

typedef unsigned long long u64;

// ---------------- device state ----------------
__device__ float g_Q[TT*NBD];
__device__ float g_K[TT*NBD];
__device__ float g_V[TT*NBD];
__device__ float g_th[TT], g_et[TT], g_al[TT];
__device__ float g_W1[DD*DD], g_M1w[DD*DD], g_b1[DD], g_M1b[DD];
__device__ float g_W2[DD*DD], g_M2w[DD*DD], g_b2[DD], g_M2b[DD];
__device__ float g_h[2*NBD];      // raw pre-activations: rows 0-63 q-path, 64-127 k-path
__device__ float g_diff[NBD];     // out - v (UNSCALED)
__device__ float g_dpre[NBD];     // masked diff@W2 (UNSCALED)
__device__ float g_gW1[DD*DD], g_gW2[DD*DD];
__device__ float g_loss[TT];
__device__ unsigned g_barcnt;
__device__ volatile unsigned g_bargen;

// ---------------- f32x2 helpers ----------------
__device__ __forceinline__ u64 pk2(float x, float y){
    u64 r; asm("mov.b64 %0, {%1, %2};" : "=l"(r) : "f"(x), "f"(y)); return r;
}
__device__ __forceinline__ void fma2(u64 &c, u64 a, u64 b){
    asm("fma.rn.f32x2 %0, %1, %2, %0;" : "+l"(c) : "l"(a), "l"(b));
}
__device__ __forceinline__ float2 up2(u64 v){
    float lo, hi; asm("mov.b64 {%0, %1}, %2;" : "=f"(lo), "=f"(hi) : "l"(v));
    return make_float2(lo, hi);
}

// ---------------- grid barrier (monotonic count; reset per launch in k_init) --------------
__device__ __forceinline__ void gbar(unsigned &gen){
    __syncthreads();
    if (threadIdx.x == 0){
        __threadfence();                         // order my writes; CCTL.IVALL
        unsigned target = (gen + 1u) * (unsigned)G_CTAS;
        unsigned arrived = atomicAdd(&g_barcnt, 1u) + 1u;
        if (arrived == target){
            g_bargen = gen + 1u;
        } else {
            while (g_bargen < gen + 1u) { __nanosleep(64); }
        }
        __threadfence();                         // invalidate L1 before reading peers' data
    }
    __syncthreads();
    gen++;
}

// ---------------- init: copy weights, zero momentum + loss + barrier ----------------
__global__ void k_init(const float* __restrict__ W1, const float* __restrict__ b1,
                       const float* __restrict__ W2, const float* __restrict__ b2) {
    int i = blockIdx.x * 256 + threadIdx.x;
    if (i < DD*DD) { g_W1[i] = W1[i]; g_M1w[i] = 0.f; g_W2[i] = W2[i]; g_M2w[i] = 0.f; }
    if (i < DD)    { g_b1[i] = b1[i]; g_M1b[i] = 0.f; g_b2[i] = b2[i]; g_M2b[i] = 0.f; }
    if (i < TT)    g_loss[i] = 0.f;
    if (i == 0)    { g_barcnt = 0u; g_bargen = 0u; }
}

// ---------------- gates ----------------
__global__ void k_gates(const float* __restrict__ x,
                        const float* __restrict__ thw, const float* __restrict__ thb,
                        const float* __restrict__ etw, const float* __restrict__ etb,
                        const float* __restrict__ alw, const float* __restrict__ alb) {
    int t = blockIdx.x, tid = threadIdx.x, lane = tid & 31, warp = tid >> 5;
    __shared__ float red[8];
    for (int g = 0; g < 3; g++) {
        const float* w = (g == 0) ? thw : ((g == 1) ? etw : alw);
        float b0 = (g == 0) ? thb[0] : ((g == 1) ? etb[0] : alb[0]);
        float acc = 0.f;
        for (int bi = warp; bi < BB; bi += 8) {
            const float* xr = x + ((size_t)bi * TT + t) * DD;
            float s = 0.f;
            for (int k = lane; k < DD; k += 32) s += xr[k] * w[k];
            #pragma unroll
            for (int o = 16; o; o >>= 1) s += __shfl_down_sync(0xffffffffu, s, o);
            if (lane == 0) acc += 1.f / (1.f + expf(-(s + b0)));
        }
        if (lane == 0) red[warp] = acc;
        __syncthreads();
        if (tid == 0) {
            float s = 0.f;
            #pragma unroll
            for (int i = 0; i < 8; i++) s += red[i];
            s *= (1.f / (float)BB);
            if (g == 0) g_th[t] = s; else if (g == 1) g_et[t] = s; else g_al[t] = s;
        }
        __syncthreads();
    }
}

// ---------------- QKV: O[m][n] = sum_k x_row(m)[k] * W[n][k], m = t*64+b ----------------
__global__ __launch_bounds__(256) void k_qkv(const float* __restrict__ x,
                       const float* __restrict__ WQ, const float* __restrict__ WK,
                       const float* __restrict__ WV) {
    __shared__ float As[64][33], Bsh[64][33];
    int n0 = blockIdx.x * 64, m0 = blockIdx.y * 64;
    const float* W = (blockIdx.z == 0) ? WQ : ((blockIdx.z == 1) ? WK : WV);
    float* O = (blockIdx.z == 0) ? g_Q : ((blockIdx.z == 1) ? g_K : g_V);
    int tid = threadIdx.x;
    int r0 = (tid >> 4) * 4, c0 = (tid & 15) * 4;
    float acc[4][4];
    #pragma unroll
    for (int i = 0; i < 4; i++)
        #pragma unroll
        for (int j = 0; j < 4; j++) acc[i][j] = 0.f;
    for (int kb = 0; kb < 16; kb++) {
        #pragma unroll
        for (int i = 0; i < 2; i++) {
            int e = tid + i*256;          // 0..511 float4 slots
            int row = e >> 3, kq = e & 7;
            int m = m0 + row;
            float4 xv = *(const float4*)&x[((size_t)(m & 63)*TT + (m >> 6))*DD + kb*32 + kq*4];
            As[row][4*kq+0]=xv.x; As[row][4*kq+1]=xv.y; As[row][4*kq+2]=xv.z; As[row][4*kq+3]=xv.w;
            float4 wv = *(const float4*)&W[(size_t)(n0 + row)*DD + kb*32 + kq*4];
            Bsh[row][4*kq+0]=wv.x; Bsh[row][4*kq+1]=wv.y; Bsh[row][4*kq+2]=wv.z; Bsh[row][4*kq+3]=wv.w;
        }
        __syncthreads();
        #pragma unroll 4
        for (int kk = 0; kk < 32; kk++) {
            float a0 = As[r0+0][kk], a1 = As[r0+1][kk], a2 = As[r0+2][kk], a3 = As[r0+3][kk];
            float b0 = Bsh[c0+0][kk], b1 = Bsh[c0+1][kk], b2 = Bsh[c0+2][kk], b3 = Bsh[c0+3][kk];
            acc[0][0]+=a0*b0; acc[0][1]+=a0*b1; acc[0][2]+=a0*b2; acc[0][3]+=a0*b3;
            acc[1][0]+=a1*b0; acc[1][1]+=a1*b1; acc[1][2]+=a1*b2; acc[1][3]+=a1*b3;
            acc[2][0]+=a2*b0; acc[2][1]+=a2*b1; acc[2][2]+=a2*b2; acc[2][3]+=a2*b3;
            acc[3][0]+=a3*b0; acc[3][1]+=a3*b1; acc[3][2]+=a3*b2; acc[3][3]+=a3*b3;
        }
        __syncthreads();
    }
    #pragma unroll
    for (int i = 0; i < 4; i++) {
        float4 v = make_float4(acc[i][0], acc[i][1], acc[i][2], acc[i][3]);
        *(float4*)&O[(size_t)(m0 + r0 + i)*DD + n0 + c0] = v;
    }
}

// ======================= persistent scan kernel =======================
#define SMBYTES 26368
__global__ __launch_bounds__(256, 1) void k_scan(float* __restrict__ out, int dup) {
    __shared__ __align__(16) unsigned char smraw[SMBYTES];
    __shared__ float red[8];
    float (*As)[512]  = (float(*)[512])smraw;                     // 16384 B
    float (*Bs)[66]   = (float(*)[66])(smraw + 8*512*4);          // +8448 B
    float (*Ag)[33]   = (float(*)[33])smraw;                      // 8448 B
    float (*Bg)[68]   = (float(*)[68])(smraw + 64*33*4);          // +17408 B

    int cta = blockIdx.x, tid = threadIdx.x;
    unsigned gen = 0;

    // ---- local lambdas as device code (written inline per phase) ----
    for (int t = 0; t < TT; t++) {
        // ======== phase U: apply update from step t-1 ========
        if (t > 0) {
            float th = g_th[t-1], et = g_et[t-1], al = g_al[t-1];
            float ls = g_loss[t-1] * (1.f/(float)NBD);
            float pt = (ls >= 1e-10f && ls <= 1e10f) ? 1.f : 0.f;
            float s  = th * pt * (2.f/(float)NBD);
            float oa = 1.f - al;
            size_t base = (size_t)cta * 2048;
            #pragma unroll
            for (int i = 0; i < 2; i++) {
                size_t idx = base + (size_t)tid*4 + (size_t)i*1024;
                float4 g1 = *(const float4*)&g_gW1[idx];
                float4 m1 = *(const float4*)&g_M1w[idx];
                float4 w1 = *(const float4*)&g_W1[idx];
                m1.x = et*m1.x - s*g1.x; w1.x = oa*w1.x + m1.x;
                m1.y = et*m1.y - s*g1.y; w1.y = oa*w1.y + m1.y;
                m1.z = et*m1.z - s*g1.z; w1.z = oa*w1.z + m1.z;
                m1.w = et*m1.w - s*g1.w; w1.w = oa*w1.w + m1.w;
                *(float4*)&g_M1w[idx] = m1; *(float4*)&g_W1[idx] = w1;
                float4 g2 = *(const float4*)&g_gW2[idx];
                float4 m2 = *(const float4*)&g_M2w[idx];
                float4 w2 = *(const float4*)&g_W2[idx];
                m2.x = et*m2.x - s*g2.x; w2.x = oa*w2.x + m2.x;
                m2.y = et*m2.y - s*g2.y; w2.y = oa*w2.y + m2.y;
                m2.z = et*m2.z - s*g2.z; w2.z = oa*w2.z + m2.z;
                m2.w = et*m2.w - s*g2.w; w2.w = oa*w2.w + m2.w;
                *(float4*)&g_M2w[idx] = m2; *(float4*)&g_W2[idx] = w2;
            }
            if (cta < 8 && tid < 128) {
                int col = (cta & 3) * 128 + tid;
                const float* src = (cta < 4) ? g_dpre : g_diff;
                float g = 0.f;
                #pragma unroll 8
                for (int b = 0; b < BB; b++) g += src[(size_t)b*DD + col];
                if (cta < 4) { float m = et*g_M1b[col] - s*g; g_M1b[col] = m; g_b1[col] = oa*g_b1[col] + m; }
                else         { float m = et*g_M2b[col] - s*g; g_M2b[col] = m; g_b2[col] = oa*g_b2[col] + m; }
            }
            gbar(gen);
        }

        // ======== phases H (mode 0) and O (mode 1): 8x64 tiles, 128 CTAs ========
        for (int mode = 0; mode < 2; mode++) {
            int m0 = (cta >> 3) * 8, n0 = (cta & 7) * 64;
            // load A tile: 8 rows x 512 k (full K)
            #pragma unroll
            for (int i = 0; i < 4; i++) {
                int e = tid + i*256;             // 0..1023 float4 slots
                int row = e >> 7, k4 = e & 127;
                int m = m0 + row;
                const float* src;
                if (mode == 0)
                    src = (m < 64) ? (g_Q + (size_t)t*NBD + (size_t)m*DD)
                                   : (g_K + (size_t)t*NBD + (size_t)(m-64)*DD);
                else
                    src = g_h + (size_t)m*DD;
                float4 v = *(const float4*)(src + k4*4);
                if (mode == 1) { v.x=fmaxf(v.x,0.f); v.y=fmaxf(v.y,0.f); v.z=fmaxf(v.z,0.f); v.w=fmaxf(v.w,0.f); }
                *(float4*)&As[row][k4*4] = v;
            }
            const float* W = (mode == 0) ? g_W1 : g_W2;
            int r = tid >> 5, c = tid & 31;
            u64 acc0 = 0ull, acc1 = 0ull;
            for (int kb = 0; kb < 16; kb++) {
                #pragma unroll
                for (int i = 0; i < 2; i++) {
                    int e = tid + i*256;         // 0..511 float4 slots
                    int n = e >> 3, kq = e & 7;
                    float4 w = *(const float4*)&W[(size_t)(n0 + n)*DD + kb*32 + kq*4];
                    Bs[4*kq+0][n]=w.x; Bs[4*kq+1][n]=w.y; Bs[4*kq+2][n]=w.z; Bs[4*kq+3][n]=w.w;
                }
                __syncthreads();
                const float* ar = &As[r][kb*32];
                #pragma unroll
                for (int kk = 0; kk < 32; kk += 2) {
                    float a0 = ar[kk], a1 = ar[kk+1];
                    u64 b0 = *(const u64*)&Bs[kk][2*c];
                    u64 b1 = *(const u64*)&Bs[kk+1][2*c];
                    fma2(acc0, pk2(a0,a0), b0);
                    fma2(acc1, pk2(a1,a1), b1);
                }
                __syncthreads();
            }
            float2 s0 = up2(acc0), s1 = up2(acc1);
            float r0v = s0.x + s1.x, r1v = s0.y + s1.y;
            int m = m0 + r, n = n0 + 2*c;
            if (mode == 0) {
                r0v += g_b1[n]; r1v += g_b1[n+1];
                *(float2*)&g_h[(size_t)m*DD + n] = make_float2(r0v, r1v);
            } else {
                r0v += g_b2[n]; r1v += g_b2[n+1];
                if (m < 64) {
                    size_t o = ((size_t)m*TT + t)*DD + n;
                    *(float2*)&out[o] = make_float2(r0v, r1v);
                    if (dup) *(float2*)&out[BTD + o] = make_float2(r0v, r1v);
                } else {
                    int b = m - 64;
                    float2 v = *(const float2*)&g_V[(size_t)t*NBD + (size_t)b*DD + n];
                    float d0 = r0v - v.x, d1 = r1v - v.y;
                    *(float2*)&g_diff[(size_t)b*DD + n] = make_float2(d0, d1);
                    float ls = d0*d0 + d1*d1;
                    #pragma unroll
                    for (int o2 = 16; o2; o2 >>= 1) ls += __shfl_down_sync(0xffffffffu, ls, o2);
                    if ((tid & 31) == 0) red[tid >> 5] = ls;
                    __syncthreads();
                    if (tid == 0) {
                        float s = 0.f;
                        #pragma unroll
                        for (int i = 0; i < 8; i++) s += red[i];
                        atomicAdd(&g_loss[t], s);
                    }
                }
            }
            gbar(gen);
            if (mode == 1 && t == TT-1) break;   // nothing after final O
        }
        if (t == TT-1) break;

        // ======== phase D: CTAs 0-63 -> dpre ; CTAs 64-127 -> gW2 ========
        if (cta < 64) {
            int m0 = (cta >> 3) * 8, n0 = (cta & 7) * 64;
            #pragma unroll
            for (int i = 0; i < 4; i++) {
                int e = tid + i*256;
                int row = e >> 7, k4 = e & 127;
                float4 v = *(const float4*)&g_diff[(size_t)(m0 + row)*DD + k4*4];
                *(float4*)&As[row][k4*4] = v;
            }
            int r = tid >> 5, c = tid & 31;
            u64 acc0 = 0ull, acc1 = 0ull;
            for (int kb = 0; kb < 16; kb++) {
                #pragma unroll
                for (int i = 0; i < 2; i++) {
                    int e = tid + i*256;
                    int kk = e >> 4, nq = e & 15;
                    float4 w = *(const float4*)&g_W2[(size_t)(kb*32 + kk)*DD + n0 + nq*4];
                    *(float2*)&Bs[kk][4*nq]   = make_float2(w.x, w.y);
                    *(float2*)&Bs[kk][4*nq+2] = make_float2(w.z, w.w);
                }
                __syncthreads();
                const float* ar = &As[r][kb*32];
                #pragma unroll
                for (int kk = 0; kk < 32; kk += 2) {
                    float a0 = ar[kk], a1 = ar[kk+1];
                    u64 b0 = *(const u64*)&Bs[kk][2*c];
                    u64 b1 = *(const u64*)&Bs[kk+1][2*c];
                    fma2(acc0, pk2(a0,a0), b0);
                    fma2(acc1, pk2(a1,a1), b1);
                }
                __syncthreads();
            }
            float2 s0 = up2(acc0), s1 = up2(acc1);
            float r0v = s0.x + s1.x, r1v = s0.y + s1.y;
            int m = m0 + r, n = n0 + 2*c;
            float2 hp = *(const float2*)&g_h[(size_t)(64 + m)*DD + n];
            float2 o;
            o.x = (hp.x > 0.f) ? r0v : 0.f;
            o.y = (hp.y > 0.f) ? r1v : 0.f;
            *(float2*)&g_dpre[(size_t)m*DD + n] = o;
        } else {
            int tbase = cta - 64;
            #pragma unroll
            for (int pass = 0; pass < 2; pass++) {
                int id = tbase + pass*64;
                int i0 = (id >> 3) * 32, j0 = (id & 7) * 64;
                #pragma unroll
                for (int i = 0; i < 8; i++) {
                    int e = tid + i*256; int b = e >> 5, ii = e & 31;
                    Ag[b][ii] = g_diff[(size_t)b*DD + i0 + ii];
                }
                #pragma unroll
                for (int i = 0; i < 4; i++) {
                    int e = tid + i*256; int b = e >> 4, jq = e & 15;
                    float4 v = *(const float4*)&g_h[(size_t)(64 + b)*DD + j0 + jq*4];
                    v.x=fmaxf(v.x,0.f); v.y=fmaxf(v.y,0.f); v.z=fmaxf(v.z,0.f); v.w=fmaxf(v.w,0.f);
                    *(float4*)&Bg[b][jq*4] = v;
                }
                __syncthreads();
                int ty = tid >> 4, tx = tid & 15;
                float acc[2][4];
                #pragma unroll
                for (int i=0;i<2;i++)
                    #pragma unroll
                    for (int j=0;j<4;j++) acc[i][j]=0.f;
                #pragma unroll 4
                for (int b = 0; b < 64; b++) {
                    float a0 = Ag[b][2*ty], a1 = Ag[b][2*ty+1];
                    float4 bv = *(const float4*)&Bg[b][4*tx];
                    acc[0][0]+=a0*bv.x; acc[0][1]+=a0*bv.y; acc[0][2]+=a0*bv.z; acc[0][3]+=a0*bv.w;
                    acc[1][0]+=a1*bv.x; acc[1][1]+=a1*bv.y; acc[1][2]+=a1*bv.z; acc[1][3]+=a1*bv.w;
                }
                __syncthreads();
                int i = i0 + 2*ty, j = j0 + 4*tx;
                *(float4*)&g_gW2[(size_t)i*DD + j]     = make_float4(acc[0][0],acc[0][1],acc[0][2],acc[0][3]);
                *(float4*)&g_gW2[(size_t)(i+1)*DD + j] = make_float4(acc[1][0],acc[1][1],acc[1][2],acc[1][3]);
            }
        }
        gbar(gen);

        // ======== phase G: gW1 = dpre^T @ k, 128 tiles ========
        {
            int i0 = (cta >> 3) * 32, j0 = (cta & 7) * 64;
            const float* Bsrc = g_K + (size_t)t*NBD;
            #pragma unroll
            for (int i = 0; i < 8; i++) {
                int e = tid + i*256; int b = e >> 5, ii = e & 31;
                Ag[b][ii] = g_dpre[(size_t)b*DD + i0 + ii];
            }
            #pragma unroll
            for (int i = 0; i < 4; i++) {
                int e = tid + i*256; int b = e >> 4, jq = e & 15;
                float4 v = *(const float4*)&Bsrc[(size_t)b*DD + j0 + jq*4];
                *(float4*)&Bg[b][jq*4] = v;
            }
            __syncthreads();
            int ty = tid >> 4, tx = tid & 15;
            float acc[2][4];
            #pragma unroll
            for (int i=0;i<2;i++)
                #pragma unroll
                for (int j=0;j<4;j++) acc[i][j]=0.f;
            #pragma unroll 4
            for (int b = 0; b < 64; b++) {
                float a0 = Ag[b][2*ty], a1 = Ag[b][2*ty+1];
                float4 bv = *(const float4*)&Bg[b][4*tx];
                acc[0][0]+=a0*bv.x; acc[0][1]+=a0*bv.y; acc[0][2]+=a0*bv.z; acc[0][3]+=a0*bv.w;
                acc[1][0]+=a1*bv.x; acc[1][1]+=a1*bv.y; acc[1][2]+=a1*bv.z; acc[1][3]+=a1*bv.w;
            }
            __syncthreads();
            int i = i0 + 2*ty, j = j0 + 4*tx;
            *(float4*)&g_gW1[(size_t)i*DD + j]     = make_float4(acc[0][0],acc[0][1],acc[0][2],acc[0][3]);
            *(float4*)&g_gW1[(size_t)(i+1)*DD + j] = make_float4(acc[1][0],acc[1][1],acc[1][2],acc[1][3]);
        }
        gbar(gen);
    }
}

// ---------------- launch ----------------
extern "C" void kernel_launch(void* const* d_in, const int* in_sizes, int n_in,
                              void* d_out, int out_size) {
    const float* x   = (const float*)d_in[0];
    const float* WQ  = (const float*)d_in[1];
    const float* WK  = (const float*)d_in[2];
    const float* WV  = (const float*)d_in[3];
    const float* thw = (const float*)d_in[4];
    const float* thb = (const float*)d_in[5];
    const float* etw = (const float*)d_in[6];
    const float* etb = (const float*)d_in[7];
    const float* alw = (const float*)d_in[8];
    const float* alb = (const float*)d_in[9];
    const float* W1  = (const float*)d_in[10];
    const float* b1  = (const float*)d_in[11];
    const float* W2  = (const float*)d_in[12];
    const float* b2  = (const float*)d_in[13];
    float* out = (float*)d_out;
    int dup = (out_size >= 2 * BTD) ? 1 : 0;

    k_init<<<1024, 256>>>(W1, b1, W2, b2);
    k_gates<<<TT, 256>>>(x, thw, thb, etw, etb, alw, alb);
    k_qkv<<<dim3(8, 128, 3), 256>>>(x, WQ, WK, WV);
    k_scan<<<G_CTAS, 256>>>(out, dup);
}

// round 7
// speedup vs baseline: 1.0444x; 1.0444x over previous
#include <cuda_runtime.h>
#include <math.h>

#define BB 64
#define TT 128
#define DD 512
#define NBD (BB*DD)
#define BTD (BB*TT*DD)
#define G_CTAS 128

typedef unsigned long long u64;

__device__ float g_Q[TT*NBD], g_K[TT*NBD], g_V[TT*NBD];
__device__ float g_th[TT], g_et[TT], g_al[TT];
__device__ float g_W1[DD*DD], g_M1w[DD*DD], g_b1[DD], g_M1b[DD];
__device__ float g_W2[DD*DD], g_M2w[DD*DD], g_b2[DD], g_M2b[DD];
__device__ float g_W1t[DD*DD], g_W2t[DD*DD];      // k-major copies
__device__ float g_h[2*NBD];                      // rows 0-63 q-path, 64-127 k-path
__device__ float g_diff[NBD], g_dpre[NBD];
__device__ float g_gW2[DD*DD];
__device__ float g_loss[TT];
__device__ unsigned g_barcnt;
__device__ volatile unsigned g_bargen;

__device__ __forceinline__ u64 pk2(float x, float y){
    u64 r; asm("mov.b64 %0, {%1, %2};" : "=l"(r) : "f"(x), "f"(y)); return r;
}
__device__ __forceinline__ void fma2(u64 &c, u64 a, u64 b){
    asm("fma.rn.f32x2 %0, %1, %2, %0;" : "+l"(c) : "l"(a), "l"(b));
}
__device__ __forceinline__ float2 up2(u64 v){
    float lo, hi; asm("mov.b64 {%0, %1}, %2;" : "=f"(lo), "=f"(hi) : "l"(v));
    return make_float2(lo, hi);
}

__device__ __forceinline__ void gbar(unsigned &gen){
    __syncthreads();
    if (threadIdx.x == 0){
        __threadfence();
        unsigned target = (gen + 1u) * (unsigned)G_CTAS;
        if (atomicAdd(&g_barcnt, 1u) + 1u == target) g_bargen = gen + 1u;
        else while (g_bargen < gen + 1u) { __nanosleep(32); }
        __threadfence();
    }
    __syncthreads();
    gen++;
}

__global__ void k_init(const float* __restrict__ W1, const float* __restrict__ b1,
                       const float* __restrict__ W2, const float* __restrict__ b2) {
    int i = blockIdx.x * 256 + threadIdx.x;
    if (i < DD*DD) {
        g_W1[i] = W1[i]; g_M1w[i] = 0.f; g_W2[i] = W2[i]; g_M2w[i] = 0.f;
        int tr = (i & 511) * 512 + (i >> 9);
        g_W1t[tr] = W1[i]; g_W2t[tr] = W2[i];
    }
    if (i < DD) { g_b1[i] = b1[i]; g_M1b[i] = 0.f; g_b2[i] = b2[i]; g_M2b[i] = 0.f; }
    if (i < TT) g_loss[i] = 0.f;
    if (i == 0) { g_barcnt = 0u; g_bargen = 0u; }
}

__global__ void k_gates(const float* __restrict__ x,
                        const float* __restrict__ thw, const float* __restrict__ thb,
                        const float* __restrict__ etw, const float* __restrict__ etb,
                        const float* __restrict__ alw, const float* __restrict__ alb) {
    int t = blockIdx.x, tid = threadIdx.x, lane = tid & 31, warp = tid >> 5;
    __shared__ float red[8];
    for (int g = 0; g < 3; g++) {
        const float* w = (g == 0) ? thw : ((g == 1) ? etw : alw);
        float b0 = (g == 0) ? thb[0] : ((g == 1) ? etb[0] : alb[0]);
        float acc = 0.f;
        for (int bi = warp; bi < BB; bi += 8) {
            const float* xr = x + ((size_t)bi * TT + t) * DD;
            float s = 0.f;
            for (int k = lane; k < DD; k += 32) s += xr[k] * w[k];
            #pragma unroll
            for (int o = 16; o; o >>= 1) s += __shfl_down_sync(0xffffffffu, s, o);
            if (lane == 0) acc += 1.f / (1.f + expf(-(s + b0)));
        }
        if (lane == 0) red[warp] = acc;
        __syncthreads();
        if (tid == 0) {
            float s = 0.f;
            #pragma unroll
            for (int i = 0; i < 8; i++) s += red[i];
            s *= (1.f / (float)BB);
            if (g == 0) g_th[t] = s; else if (g == 1) g_et[t] = s; else g_al[t] = s;
        }
        __syncthreads();
    }
}

__global__ __launch_bounds__(256) void k_qkv(const float* __restrict__ x,
                       const float* __restrict__ WQ, const float* __restrict__ WK,
                       const float* __restrict__ WV) {
    __shared__ float As[64][33], Bsh[64][33];
    int n0 = blockIdx.x * 64, m0 = blockIdx.y * 64;
    const float* W = (blockIdx.z == 0) ? WQ : ((blockIdx.z == 1) ? WK : WV);
    float* O = (blockIdx.z == 0) ? g_Q : ((blockIdx.z == 1) ? g_K : g_V);
    int tid = threadIdx.x;
    int r0 = (tid >> 4) * 4, c0 = (tid & 15) * 4;
    float acc[4][4];
    #pragma unroll
    for (int i = 0; i < 4; i++)
        #pragma unroll
        for (int j = 0; j < 4; j++) acc[i][j] = 0.f;
    for (int kb = 0; kb < 16; kb++) {
        #pragma unroll
        for (int i = 0; i < 2; i++) {
            int e = tid + i*256;
            int row = e >> 3, kq = e & 7;
            int m = m0 + row;
            float4 xv = *(const float4*)&x[((size_t)(m & 63)*TT + (m >> 6))*DD + kb*32 + kq*4];
            As[row][4*kq+0]=xv.x; As[row][4*kq+1]=xv.y; As[row][4*kq+2]=xv.z; As[row][4*kq+3]=xv.w;
            float4 wv = *(const float4*)&W[(size_t)(n0 + row)*DD + kb*32 + kq*4];
            Bsh[row][4*kq+0]=wv.x; Bsh[row][4*kq+1]=wv.y; Bsh[row][4*kq+2]=wv.z; Bsh[row][4*kq+3]=wv.w;
        }
        __syncthreads();
        #pragma unroll 4
        for (int kk = 0; kk < 32; kk++) {
            float a0 = As[r0+0][kk], a1 = As[r0+1][kk], a2 = As[r0+2][kk], a3 = As[r0+3][kk];
            float b0 = Bsh[c0+0][kk], b1 = Bsh[c0+1][kk], b2 = Bsh[c0+2][kk], b3 = Bsh[c0+3][kk];
            acc[0][0]+=a0*b0; acc[0][1]+=a0*b1; acc[0][2]+=a0*b2; acc[0][3]+=a0*b3;
            acc[1][0]+=a1*b0; acc[1][1]+=a1*b1; acc[1][2]+=a1*b2; acc[1][3]+=a1*b3;
            acc[2][0]+=a2*b0; acc[2][1]+=a2*b1; acc[2][2]+=a2*b2; acc[2][3]+=a2*b3;
            acc[3][0]+=a3*b0; acc[3][1]+=a3*b1; acc[3][2]+=a3*b2; acc[3][3]+=a3*b3;
        }
        __syncthreads();
    }
    #pragma unroll
    for (int i = 0; i < 4; i++)
        *(float4*)&O[(size_t)(m0 + r0 + i)*DD + n0 + c0] =
            make_float4(acc[i][0], acc[i][1], acc[i][2], acc[i][3]);
}

// streamed GEMM: C[8 x 64] = A8(8x512) @ Bk(k-major, stride 512), depth-2 prefetch.
// thread (r=tid>>5, c2=(tid&31)*2) produces outputs (r, c2),(r, c2+1).
__device__ __forceinline__ float2 sgemm(const float* __restrict__ A8,
                                        const float* __restrict__ Bk,
                                        bool reluA, float* sm, int tid) {
    float (*As)[512] = (float(*)[512])sm;
    float (*Bs)[68]  = (float(*)[68])(sm + 8*512);   // 68-float stride: 272B, float4-safe
    float4 br[2][4];
    #pragma unroll
    for (int j = 0; j < 4; j++) {
        int e = tid + j*256; int kq = e >> 4, nq = e & 15;
        br[0][j] = *(const float4*)&Bk[(size_t)kq*512 + nq*4];
        br[1][j] = *(const float4*)&Bk[(size_t)(64 + kq)*512 + nq*4];
    }
    #pragma unroll
    for (int i = 0; i < 4; i++) {
        int e = tid + i*256; int row = e >> 7, k4 = e & 127;
        float4 v = *(const float4*)&A8[(size_t)row*512 + k4*4];
        if (reluA) { v.x=fmaxf(v.x,0.f); v.y=fmaxf(v.y,0.f); v.z=fmaxf(v.z,0.f); v.w=fmaxf(v.w,0.f); }
        *(float4*)&As[row][k4*4] = v;
    }
    #pragma unroll
    for (int j = 0; j < 4; j++) {
        int e = tid + j*256; int kq = e >> 4, nq = e & 15;
        *(float4*)&Bs[kq][nq*4] = br[0][j];
    }
    __syncthreads();
    u64 acc0 = 0ull, acc1 = 0ull, acc2 = 0ull, acc3 = 0ull;
    int r = tid >> 5, c2 = (tid & 31) * 2;
    for (int ck = 0; ck < 8; ck++) {
        const float* ar = &As[r][ck*64];
        #pragma unroll
        for (int kk = 0; kk < 64; kk += 4) {
            float4 a = *(const float4*)&ar[kk];
            fma2(acc0, pk2(a.x,a.x), *(const u64*)&Bs[kk  ][c2]);
            fma2(acc1, pk2(a.y,a.y), *(const u64*)&Bs[kk+1][c2]);
            fma2(acc2, pk2(a.z,a.z), *(const u64*)&Bs[kk+2][c2]);
            fma2(acc3, pk2(a.w,a.w), *(const u64*)&Bs[kk+3][c2]);
        }
        __syncthreads();
        if (ck < 7) {
            #pragma unroll
            for (int j = 0; j < 4; j++) {
                int e = tid + j*256; int kq = e >> 4, nq = e & 15;
                *(float4*)&Bs[kq][nq*4] = br[(ck+1)&1][j];
            }
            if (ck < 6) {
                #pragma unroll
                for (int j = 0; j < 4; j++) {
                    int e = tid + j*256; int kq = e >> 4, nq = e & 15;
                    br[ck&1][j] = *(const float4*)&Bk[(size_t)((ck+2)*64 + kq)*512 + nq*4];
                }
            }
            __syncthreads();
        }
    }
    float2 s0 = up2(acc0), s1 = up2(acc1), s2 = up2(acc2), s3 = up2(acc3);
    return make_float2(s0.x + s1.x + s2.x + s3.x, s0.y + s1.y + s2.y + s3.y);
}

__global__ __launch_bounds__(256, 1) void k_scan(float* __restrict__ out, int dup) {
    __shared__ __align__(16) float sm[9600];   // 38.4KB
    __shared__ float red[8];
    int cta = blockIdx.x, tid = threadIdx.x;
    unsigned gen = 0;

    for (int t = 0; t < TT; t++) {
        // ---- U: fused gW1 GEMM + weight/bias updates (grads of step t-1) ----
        if (t > 0) {
            float th = g_th[t-1], et = g_et[t-1], al = g_al[t-1];
            float ls = g_loss[t-1] * (1.f/(float)NBD);
            float pt = (ls >= 1e-10f && ls <= 1e10f) ? 1.f : 0.f;
            float s  = th * pt * (2.f/(float)NBD);
            float oa = 1.f - al;
            int i0 = (cta >> 2) * 16, j0 = (cta & 3) * 128;
            float (*sDp)[17]  = (float(*)[17])sm;               // 64x17
            float (*sK)[132]  = (float(*)[132])(sm + 64*17);    // 64x132
            #pragma unroll
            for (int i = 0; i < 4; i++) {
                int e = tid + i*256; int b = e >> 4, ii = e & 15;
                sDp[b][ii] = g_dpre[(size_t)b*DD + i0 + ii];
            }
            const float* Kt = g_K + (size_t)(t-1)*NBD;
            #pragma unroll
            for (int i = 0; i < 8; i++) {
                int e = tid + i*256; int b = e >> 5, jq = e & 31;
                *(float4*)&sK[b][jq*4] = *(const float4*)&Kt[(size_t)b*DD + j0 + jq*4];
            }
            __syncthreads();
            int ti = tid >> 4, tj = tid & 15;
            u64 a0 = 0ull, a1 = 0ull, a2 = 0ull, a3 = 0ull;
            #pragma unroll 4
            for (int b = 0; b < 64; b++) {
                u64 as = pk2(sDp[b][ti], sDp[b][ti]);
                const float* kp = &sK[b][tj*8];
                ulonglong2 p = *(const ulonglong2*)kp;
                ulonglong2 q = *(const ulonglong2*)(kp + 4);
                fma2(a0, as, p.x); fma2(a1, as, p.y); fma2(a2, as, q.x); fma2(a3, as, q.y);
            }
            float gv[8];
            { float2 u; u = up2(a0); gv[0]=u.x; gv[1]=u.y; u = up2(a1); gv[2]=u.x; gv[3]=u.y;
              u = up2(a2); gv[4]=u.x; gv[5]=u.y; u = up2(a3); gv[6]=u.x; gv[7]=u.y; }
            int iw = i0 + ti, jw = j0 + tj*8;
            size_t idx = (size_t)iw*DD + jw;
            float wn[8];
            #pragma unroll
            for (int h = 0; h < 2; h++) {
                float4 mm = *(const float4*)&g_M1w[idx + h*4];
                float4 ww = *(const float4*)&g_W1[idx + h*4];
                mm.x = et*mm.x - s*gv[h*4+0]; ww.x = oa*ww.x + mm.x;
                mm.y = et*mm.y - s*gv[h*4+1]; ww.y = oa*ww.y + mm.y;
                mm.z = et*mm.z - s*gv[h*4+2]; ww.z = oa*ww.z + mm.z;
                mm.w = et*mm.w - s*gv[h*4+3]; ww.w = oa*ww.w + mm.w;
                *(float4*)&g_M1w[idx + h*4] = mm; *(float4*)&g_W1[idx + h*4] = ww;
                wn[h*4]=ww.x; wn[h*4+1]=ww.y; wn[h*4+2]=ww.z; wn[h*4+3]=ww.w;
            }
            #pragma unroll
            for (int l = 0; l < 8; l++) g_W1t[(size_t)(jw+l)*DD + iw] = wn[l];
            #pragma unroll
            for (int h = 0; h < 2; h++) {
                float4 gg = *(const float4*)&g_gW2[idx + h*4];
                float4 mm = *(const float4*)&g_M2w[idx + h*4];
                float4 ww = *(const float4*)&g_W2[idx + h*4];
                mm.x = et*mm.x - s*gg.x; ww.x = oa*ww.x + mm.x;
                mm.y = et*mm.y - s*gg.y; ww.y = oa*ww.y + mm.y;
                mm.z = et*mm.z - s*gg.z; ww.z = oa*ww.z + mm.z;
                mm.w = et*mm.w - s*gg.w; ww.w = oa*ww.w + mm.w;
                *(float4*)&g_M2w[idx + h*4] = mm; *(float4*)&g_W2[idx + h*4] = ww;
                wn[h*4]=ww.x; wn[h*4+1]=ww.y; wn[h*4+2]=ww.z; wn[h*4+3]=ww.w;
            }
            #pragma unroll
            for (int l = 0; l < 8; l++) g_W2t[(size_t)(jw+l)*DD + iw] = wn[l];
            if ((cta & 3) == 0) {
                if (tj == 0) {
                    float g = 0.f;
                    #pragma unroll 8
                    for (int b = 0; b < 64; b++) g += sDp[b][ti];
                    float m = et*g_M1b[iw] - s*g; g_M1b[iw] = m; g_b1[iw] = oa*g_b1[iw] + m;
                } else if (tj == 1) {
                    float g = 0.f;
                    #pragma unroll 8
                    for (int b = 0; b < 64; b++) g += g_diff[(size_t)b*DD + iw];
                    float m = et*g_M2b[iw] - s*g; g_M2b[iw] = m; g_b2[iw] = oa*g_b2[iw] + m;
                }
            }
            gbar(gen);
        }

        int m0 = (cta >> 3) * 8, n0 = (cta & 7) * 64;
        int r = tid >> 5, c2 = (tid & 31) * 2;
        int m = m0 + r, n = n0 + c2;

        // ---- H: h = [q;k] @ W1^T + b1 ----
        {
            const float* A8 = (m0 < 64) ? (g_Q + (size_t)t*NBD + (size_t)m0*DD)
                                        : (g_K + (size_t)t*NBD + (size_t)(m0-64)*DD);
            float2 rv = sgemm(A8, g_W1t + n0, false, sm, tid);
            rv.x += g_b1[n]; rv.y += g_b1[n+1];
            *(float2*)&g_h[(size_t)m*DD + n] = rv;
        }
        gbar(gen);

        // ---- O: out = relu(h) @ W2^T + b2 ; diff/loss on k-path ----
        {
            float2 rv = sgemm(g_h + (size_t)m0*DD, g_W2t + n0, true, sm, tid);
            rv.x += g_b2[n]; rv.y += g_b2[n+1];
            if (m0 < 64) {
                size_t o = ((size_t)m*TT + t)*DD + n;
                *(float2*)&out[o] = rv;
                if (dup) *(float2*)&out[BTD + o] = rv;
            } else {
                int b = m - 64;
                float2 v = *(const float2*)&g_V[(size_t)t*NBD + (size_t)b*DD + n];
                float d0 = rv.x - v.x, d1 = rv.y - v.y;
                *(float2*)&g_diff[(size_t)b*DD + n] = make_float2(d0, d1);
                float lsv = d0*d0 + d1*d1;
                #pragma unroll
                for (int o2 = 16; o2; o2 >>= 1) lsv += __shfl_down_sync(0xffffffffu, lsv, o2);
                if ((tid & 31) == 0) red[tid >> 5] = lsv;
                __syncthreads();
                if (tid == 0) {
                    float sv = 0.f;
                    #pragma unroll
                    for (int i = 0; i < 8; i++) sv += red[i];
                    atomicAdd(&g_loss[t], sv);
                }
            }
        }
        if (t == TT-1) break;
        gbar(gen);

        // ---- D: CTAs 0-63 dpre = mask(h_k>0)*(diff @ W2); CTAs 64-127 gW2 ----
        if (cta < 64) {
            float2 rv = sgemm(g_diff + (size_t)m0*DD, g_W2 + n0, false, sm, tid);
            float2 hp = *(const float2*)&g_h[(size_t)(64 + m)*DD + n];
            *(float2*)&g_dpre[(size_t)m*DD + n] =
                make_float2(hp.x > 0.f ? rv.x : 0.f, hp.y > 0.f ? rv.y : 0.f);
        } else {
            float (*Ag)[33] = (float(*)[33])sm;              // 64x33
            float (*Bg)[68] = (float(*)[68])(sm + 64*33);    // 64x68
            #pragma unroll
            for (int pass = 0; pass < 2; pass++) {
                int id = (cta - 64) + pass*64;
                int i0 = (id >> 3) * 32, j0 = (id & 7) * 64;
                #pragma unroll
                for (int i = 0; i < 8; i++) {
                    int e = tid + i*256; int b = e >> 5, ii = e & 31;
                    Ag[b][ii] = g_diff[(size_t)b*DD + i0 + ii];
                }
                #pragma unroll
                for (int i = 0; i < 4; i++) {
                    int e = tid + i*256; int b = e >> 4, jq = e & 15;
                    float4 v = *(const float4*)&g_h[(size_t)(64 + b)*DD + j0 + jq*4];
                    v.x=fmaxf(v.x,0.f); v.y=fmaxf(v.y,0.f); v.z=fmaxf(v.z,0.f); v.w=fmaxf(v.w,0.f);
                    *(float4*)&Bg[b][jq*4] = v;
                }
                __syncthreads();
                int ty = tid >> 4, tx = tid & 15;
                u64 q0 = 0ull, q1 = 0ull, q2 = 0ull, q3 = 0ull;
                #pragma unroll 4
                for (int b = 0; b < 64; b++) {
                    u64 s0 = pk2(Ag[b][2*ty], Ag[b][2*ty]);
                    u64 s1 = pk2(Ag[b][2*ty+1], Ag[b][2*ty+1]);
                    ulonglong2 bv = *(const ulonglong2*)&Bg[b][4*tx];
                    fma2(q0, s0, bv.x); fma2(q1, s0, bv.y);
                    fma2(q2, s1, bv.x); fma2(q3, s1, bv.y);
                }
                __syncthreads();
                int i = i0 + 2*ty, j = j0 + 4*tx;
                float2 p0 = up2(q0), p1 = up2(q1), p2 = up2(q2), p3 = up2(q3);
                *(float4*)&g_gW2[(size_t)i*DD + j]     = make_float4(p0.x, p0.y, p1.x, p1.y);
                *(float4*)&g_gW2[(size_t)(i+1)*DD + j] = make_float4(p2.x, p2.y, p3.x, p3.y);
            }
        }
        gbar(gen);
    }
}

extern "C" void kernel_launch(void* const* d_in, const int* in_sizes, int n_in,
                              void* d_out, int out_size) {
    const float* x   = (const float*)d_in[0];
    const float* WQ  = (const float*)d_in[1];
    const float* WK  = (const float*)d_in[2];
    const float* WV  = (const float*)d_in[3];
    const float* thw = (const float*)d_in[4];
    const float* thb = (const float*)d_in[5];
    const float* etw = (const float*)d_in[6];
    const float* etb = (const float*)d_in[7];
    const float* alw = (const float*)d_in[8];
    const float* alb = (const float*)d_in[9];
    const float* W1  = (const float*)d_in[10];
    const float* b1  = (const float*)d_in[11];
    const float* W2  = (const float*)d_in[12];
    const float* b2  = (const float*)d_in[13];
    float* out = (float*)d_out;
    int dup = (out_size >= 2 * BTD) ? 1 : 0;

    k_init<<<1024, 256>>>(W1, b1, W2, b2);
    k_gates<<<TT, 256>>>(x, thw, thb, etw, etb, alw, alb);
    k_qkv<<<dim3(8, 128, 3), 256>>>(x, WQ, WK, WV);
    k_scan<<<G_CTAS, 256>>>(out, dup);
}

// round 8
// speedup vs baseline: 1.4009x; 1.3414x over previous
#include <cuda_runtime.h>
#include <math.h>

#define BB 64
#define TT 128
#define DD 512
#define NBD (BB*DD)
#define BTD (BB*TT*DD)
#define G_CTAS 128

typedef unsigned long long u64;

__device__ float g_Qt[TT*NBD];     // [t][k][b]  (64 b per row)
__device__ float g_Kt[TT*NBD];     // [t][k][b]
__device__ float g_K [TT*NBD];     // [t][b][k]
__device__ float g_V [TT*NBD];     // [t][b][k]
__device__ float g_th[TT], g_et[TT], g_al[TT];
__device__ float g_W1[DD*DD], g_M1w[DD*DD], g_b1[DD], g_M1b[DD];
__device__ float g_W2[DD*DD], g_M2w[DD*DD], g_b2[DD], g_M2b[DD];
__device__ float g_W1t[DD*DD], g_W2t[DD*DD];   // [k][n]
__device__ float g_h[2*NBD];       // rows 0-63 q-path, 64-127 k-path
__device__ float g_ht[2*NBD];      // [n][m]  (128 m per row)
__device__ float g_diff[NBD];      // [b][n]
__device__ float g_difft[NBD];     // [n][b]  (64 b per row)
__device__ float g_dpre[NBD];      // [b][n]
__device__ float g_gW2[DD*DD];
__device__ float g_loss[TT];
__device__ unsigned g_barcnt;
__device__ volatile unsigned g_bargen;

__device__ __forceinline__ u64 pk2(float x, float y){
    u64 r; asm("mov.b64 %0, {%1, %2};" : "=l"(r) : "f"(x), "f"(y)); return r;
}
__device__ __forceinline__ void fma2(u64 &c, u64 a, u64 b){
    asm("fma.rn.f32x2 %0, %1, %2, %0;" : "+l"(c) : "l"(a), "l"(b));
}
__device__ __forceinline__ float2 up2(u64 v){
    float lo, hi; asm("mov.b64 {%0, %1}, %2;" : "=f"(lo), "=f"(hi) : "l"(v));
    return make_float2(lo, hi);
}

__device__ __forceinline__ void gbar(unsigned &gen){
    __syncthreads();
    if (threadIdx.x == 0){
        __threadfence();
        unsigned target = (gen + 1u) * (unsigned)G_CTAS;
        if (atomicAdd(&g_barcnt, 1u) + 1u == target) g_bargen = gen + 1u;
        else while (g_bargen < gen + 1u) { __nanosleep(32); }
        __threadfence();
    }
    __syncthreads();
    gen++;
}

__global__ void k_init(const float* __restrict__ W1, const float* __restrict__ b1,
                       const float* __restrict__ W2, const float* __restrict__ b2) {
    int i = blockIdx.x * 256 + threadIdx.x;
    if (i < DD*DD) {
        g_W1[i] = W1[i]; g_M1w[i] = 0.f; g_W2[i] = W2[i]; g_M2w[i] = 0.f;
        int tr = (i & 511) * 512 + (i >> 9);
        g_W1t[tr] = W1[i]; g_W2t[tr] = W2[i];
    }
    if (i < DD) { g_b1[i] = b1[i]; g_M1b[i] = 0.f; g_b2[i] = b2[i]; g_M2b[i] = 0.f; }
    if (i < TT) g_loss[i] = 0.f;
    if (i == 0) { g_barcnt = 0u; g_bargen = 0u; }
}

__global__ void k_gates(const float* __restrict__ x,
                        const float* __restrict__ thw, const float* __restrict__ thb,
                        const float* __restrict__ etw, const float* __restrict__ etb,
                        const float* __restrict__ alw, const float* __restrict__ alb) {
    int t = blockIdx.x, tid = threadIdx.x, lane = tid & 31, warp = tid >> 5;
    __shared__ float red[8];
    for (int g = 0; g < 3; g++) {
        const float* w = (g == 0) ? thw : ((g == 1) ? etw : alw);
        float b0 = (g == 0) ? thb[0] : ((g == 1) ? etb[0] : alb[0]);
        float acc = 0.f;
        for (int bi = warp; bi < BB; bi += 8) {
            const float* xr = x + ((size_t)bi * TT + t) * DD;
            float s = 0.f;
            for (int k = lane; k < DD; k += 32) s += xr[k] * w[k];
            #pragma unroll
            for (int o = 16; o; o >>= 1) s += __shfl_down_sync(0xffffffffu, s, o);
            if (lane == 0) acc += 1.f / (1.f + expf(-(s + b0)));
        }
        if (lane == 0) red[warp] = acc;
        __syncthreads();
        if (tid == 0) {
            float s = 0.f;
            #pragma unroll
            for (int i = 0; i < 8; i++) s += red[i];
            s *= (1.f / (float)BB);
            if (g == 0) g_th[t] = s; else if (g == 1) g_et[t] = s; else g_al[t] = s;
        }
        __syncthreads();
    }
}

__global__ __launch_bounds__(256) void k_qkv(const float* __restrict__ x,
                       const float* __restrict__ WQ, const float* __restrict__ WK,
                       const float* __restrict__ WV) {
    __shared__ float As[64][33], Bsh[64][33];
    int n0 = blockIdx.x * 64, m0 = blockIdx.y * 64, z = blockIdx.z;
    const float* W = (z == 0) ? WQ : ((z == 1) ? WK : WV);
    int tid = threadIdx.x;
    int r0 = (tid >> 4) * 4, c0 = (tid & 15) * 4;
    float acc[4][4];
    #pragma unroll
    for (int i = 0; i < 4; i++)
        #pragma unroll
        for (int j = 0; j < 4; j++) acc[i][j] = 0.f;
    for (int kb = 0; kb < 16; kb++) {
        #pragma unroll
        for (int i = 0; i < 2; i++) {
            int e = tid + i*256;
            int row = e >> 3, kq = e & 7;
            int m = m0 + row;
            float4 xv = *(const float4*)&x[((size_t)(m & 63)*TT + (m >> 6))*DD + kb*32 + kq*4];
            As[row][4*kq+0]=xv.x; As[row][4*kq+1]=xv.y; As[row][4*kq+2]=xv.z; As[row][4*kq+3]=xv.w;
            float4 wv = *(const float4*)&W[(size_t)(n0 + row)*DD + kb*32 + kq*4];
            Bsh[row][4*kq+0]=wv.x; Bsh[row][4*kq+1]=wv.y; Bsh[row][4*kq+2]=wv.z; Bsh[row][4*kq+3]=wv.w;
        }
        __syncthreads();
        #pragma unroll 4
        for (int kk = 0; kk < 32; kk++) {
            float a0 = As[r0+0][kk], a1 = As[r0+1][kk], a2 = As[r0+2][kk], a3 = As[r0+3][kk];
            float b0 = Bsh[c0+0][kk], b1 = Bsh[c0+1][kk], b2 = Bsh[c0+2][kk], b3 = Bsh[c0+3][kk];
            acc[0][0]+=a0*b0; acc[0][1]+=a0*b1; acc[0][2]+=a0*b2; acc[0][3]+=a0*b3;
            acc[1][0]+=a1*b0; acc[1][1]+=a1*b1; acc[1][2]+=a1*b2; acc[1][3]+=a1*b3;
            acc[2][0]+=a2*b0; acc[2][1]+=a2*b1; acc[2][2]+=a2*b2; acc[2][3]+=a2*b3;
            acc[3][0]+=a3*b0; acc[3][1]+=a3*b1; acc[3][2]+=a3*b2; acc[3][3]+=a3*b3;
        }
        __syncthreads();
    }
    int tl = m0 >> 6;
    #pragma unroll
    for (int i = 0; i < 4; i++) {
        int mrow = m0 + r0 + i, b = mrow & 63;
        float4 v = make_float4(acc[i][0], acc[i][1], acc[i][2], acc[i][3]);
        if (z == 2) { *(float4*)&g_V[(size_t)mrow*DD + n0 + c0] = v; }
        else {
            float* Ot = (z == 0) ? g_Qt : g_Kt;
            if (z == 1) *(float4*)&g_K[(size_t)mrow*DD + n0 + c0] = v;
            #pragma unroll
            for (int j = 0; j < 4; j++)
                Ot[(size_t)tl*NBD + (size_t)(n0 + c0 + j)*64 + b] = acc[i][j];
        }
    }
}

// C[8x64] = A(k-major [512][Ms], rows moff..moff+8) @ B(k-major [512][n], stride 512)
// split-K x4 across warps + smem reduce. Output: thread (tid>>5, (tid&31)*2).
__device__ __forceinline__ float2 sgemm2(const float* __restrict__ Akt, int Ms, int moff,
                                         const float* __restrict__ Bk, bool reluA,
                                         float* sm, int tid) {
    float* At = sm;                                    // [k*8 + m] 4096
    float (*Bs)[68] = (float(*)[68])(sm + 4096);       // 64 x 68
    float* sred = sm + 4096 + 64*68;                   // 256 x 10
    float4 br[2][4];
    #pragma unroll
    for (int j = 0; j < 4; j++) {
        int e = tid + j*256; int kq = e >> 4, nq = e & 15;
        br[0][j] = *(const float4*)&Bk[(size_t)kq*DD + nq*4];
        br[1][j] = *(const float4*)&Bk[(size_t)(64 + kq)*DD + nq*4];
    }
    #pragma unroll
    for (int i = 0; i < 4; i++) {
        int e = tid + i*256; int k = e >> 1, mq = (e & 1) * 4;
        float4 v = *(const float4*)&Akt[(size_t)k*Ms + moff + mq];
        if (reluA) { v.x=fmaxf(v.x,0.f); v.y=fmaxf(v.y,0.f); v.z=fmaxf(v.z,0.f); v.w=fmaxf(v.w,0.f); }
        *(float4*)&At[k*8 + mq] = v;
    }
    #pragma unroll
    for (int j = 0; j < 4; j++) {
        int e = tid + j*256; int kq = e >> 4, nq = e & 15;
        *(float4*)&Bs[kq][nq*4] = br[0][j];
    }
    __syncthreads();
    int ks = tid >> 6, rq = (tid >> 5) & 1, cv = tid & 31;
    u64 ac0=0ull, ac1=0ull, ac2=0ull, ac3=0ull;
    for (int ck = 0; ck < 8; ck++) {
        const float* ap = At + (ck*64 + ks*16)*8 + rq*4;
        const float* bp = &Bs[ks*16][2*cv];
        #pragma unroll
        for (int kk = 0; kk < 16; kk++) {
            float4 a = *(const float4*)(ap + kk*8);
            u64 b = *(const u64*)(bp + kk*68);
            fma2(ac0, pk2(a.x,a.x), b);
            fma2(ac1, pk2(a.y,a.y), b);
            fma2(ac2, pk2(a.z,a.z), b);
            fma2(ac3, pk2(a.w,a.w), b);
        }
        __syncthreads();
        if (ck < 7) {
            #pragma unroll
            for (int j = 0; j < 4; j++) {
                int e = tid + j*256; int kq = e >> 4, nq = e & 15;
                *(float4*)&Bs[kq][nq*4] = br[(ck+1)&1][j];
            }
            if (ck < 6) {
                #pragma unroll
                for (int j = 0; j < 4; j++) {
                    int e = tid + j*256; int kq = e >> 4, nq = e & 15;
                    br[ck&1][j] = *(const float4*)&Bk[(size_t)((ck+2)*64 + kq)*DD + nq*4];
                }
            }
            __syncthreads();
        }
    }
    u64* rp = (u64*)&sred[tid*10];
    rp[0]=ac0; rp[1]=ac1; rp[2]=ac2; rp[3]=ac3;
    __syncthreads();
    int r = tid >> 5, c2 = tid & 31, rq2 = r >> 2, ri = r & 3;
    float2 T = make_float2(0.f, 0.f);
    #pragma unroll
    for (int k2 = 0; k2 < 4; k2++) {
        float2 f = up2(*(const u64*)&sred[((k2*2 + rq2)*32 + c2)*10 + ri*2]);
        T.x += f.x; T.y += f.y;
    }
    return T;
}

__global__ __launch_bounds__(256, 1) void k_scan(float* __restrict__ out, int dup) {
    __shared__ __align__(16) float sm[11008];
    __shared__ float red[8];
    int cta = blockIdx.x, tid = threadIdx.x;
    unsigned gen = 0;

    for (int t = 0; t < TT; t++) {
        // ---- U: fused gW1 + all weight/bias updates (grads of t-1) ----
        if (t > 0) {
            float th = g_th[t-1], et = g_et[t-1], al = g_al[t-1];
            float ls = g_loss[t-1] * (1.f/(float)NBD);
            float pt = (ls >= 1e-10f && ls <= 1e10f) ? 1.f : 0.f;
            float s  = th * pt * (2.f/(float)NBD);
            float oa = 1.f - al;
            int i0 = (cta >> 3) * 32, j0 = (cta & 7) * 64;
            float (*sDp)[36] = (float(*)[36])sm;
            float (*sK)[68]  = (float(*)[68])(sm + 64*36);
            #pragma unroll
            for (int i = 0; i < 2; i++) {
                int e = tid + i*256; int b = e >> 3, iq = e & 7;
                *(float4*)&sDp[b][iq*4] = *(const float4*)&g_dpre[(size_t)b*DD + i0 + iq*4];
            }
            const float* Kt = g_K + (size_t)(t-1)*NBD;
            #pragma unroll
            for (int i = 0; i < 4; i++) {
                int e = tid + i*256; int b = e >> 4, jq = e & 15;
                *(float4*)&sK[b][jq*4] = *(const float4*)&Kt[(size_t)b*DD + j0 + jq*4];
            }
            __syncthreads();
            int ti = tid >> 4, tj = tid & 15;
            u64 a00=0ull, a01=0ull, a10=0ull, a11=0ull;
            #pragma unroll 8
            for (int b = 0; b < 64; b++) {
                float2 av = *(const float2*)&sDp[b][ti*2];
                ulonglong2 bv = *(const ulonglong2*)&sK[b][tj*4];
                u64 s0 = pk2(av.x,av.x), s1 = pk2(av.y,av.y);
                fma2(a00,s0,bv.x); fma2(a01,s0,bv.y);
                fma2(a10,s1,bv.x); fma2(a11,s1,bv.y);
            }
            float gr[2][4];
            { float2 p;
              p=up2(a00); gr[0][0]=p.x; gr[0][1]=p.y; p=up2(a01); gr[0][2]=p.x; gr[0][3]=p.y;
              p=up2(a10); gr[1][0]=p.x; gr[1][1]=p.y; p=up2(a11); gr[1][2]=p.x; gr[1][3]=p.y; }
            #pragma unroll
            for (int h = 0; h < 2; h++) {
                int iw = i0 + ti*2 + h, jw = j0 + tj*4;
                size_t idx = (size_t)iw*DD + jw;
                float4 mm = *(const float4*)&g_M1w[idx];
                float4 ww = *(const float4*)&g_W1[idx];
                mm.x = et*mm.x - s*gr[h][0]; ww.x = oa*ww.x + mm.x;
                mm.y = et*mm.y - s*gr[h][1]; ww.y = oa*ww.y + mm.y;
                mm.z = et*mm.z - s*gr[h][2]; ww.z = oa*ww.z + mm.z;
                mm.w = et*mm.w - s*gr[h][3]; ww.w = oa*ww.w + mm.w;
                *(float4*)&g_M1w[idx] = mm; *(float4*)&g_W1[idx] = ww;
                g_W1t[(size_t)(jw+0)*DD + iw] = ww.x; g_W1t[(size_t)(jw+1)*DD + iw] = ww.y;
                g_W1t[(size_t)(jw+2)*DD + iw] = ww.z; g_W1t[(size_t)(jw+3)*DD + iw] = ww.w;
                float4 gg = *(const float4*)&g_gW2[idx];
                mm = *(const float4*)&g_M2w[idx];
                ww = *(const float4*)&g_W2[idx];
                mm.x = et*mm.x - s*gg.x; ww.x = oa*ww.x + mm.x;
                mm.y = et*mm.y - s*gg.y; ww.y = oa*ww.y + mm.y;
                mm.z = et*mm.z - s*gg.z; ww.z = oa*ww.z + mm.z;
                mm.w = et*mm.w - s*gg.w; ww.w = oa*ww.w + mm.w;
                *(float4*)&g_M2w[idx] = mm; *(float4*)&g_W2[idx] = ww;
                g_W2t[(size_t)(jw+0)*DD + iw] = ww.x; g_W2t[(size_t)(jw+1)*DD + iw] = ww.y;
                g_W2t[(size_t)(jw+2)*DD + iw] = ww.z; g_W2t[(size_t)(jw+3)*DD + iw] = ww.w;
            }
            if ((cta & 7) == 0 && tid < 64) {
                if (tid < 32) {
                    int iw = i0 + tid; float g = 0.f;
                    #pragma unroll 8
                    for (int b = 0; b < 64; b++) g += sDp[b][tid];
                    float m = et*g_M1b[iw] - s*g; g_M1b[iw] = m; g_b1[iw] = oa*g_b1[iw] + m;
                } else {
                    int iw = i0 + tid - 32; float g = 0.f;
                    const float* dp = g_difft + (size_t)iw*64;
                    #pragma unroll
                    for (int b = 0; b < 64; b += 4) {
                        float4 v = *(const float4*)&dp[b];
                        g += v.x + v.y + v.z + v.w;
                    }
                    float m = et*g_M2b[iw] - s*g; g_M2b[iw] = m; g_b2[iw] = oa*g_b2[iw] + m;
                }
            }
            gbar(gen);
        }

        int m0 = (cta >> 3) * 8, n0 = (cta & 7) * 64;
        int r = tid >> 5, c2 = (tid & 31) * 2;
        int m = m0 + r, n = n0 + c2;

        // ---- H ----
        {
            const float* Akt = (m0 < 64) ? (g_Qt + (size_t)t*NBD) : (g_Kt + (size_t)t*NBD);
            int moff = (m0 < 64) ? m0 : (m0 - 64);
            float2 rv = sgemm2(Akt, 64, moff, g_W1t + n0, false, sm, tid);
            rv.x += g_b1[n]; rv.y += g_b1[n+1];
            *(float2*)&g_h[(size_t)m*DD + n] = rv;
            g_ht[(size_t)n*128 + m] = rv.x; g_ht[(size_t)(n+1)*128 + m] = rv.y;
        }
        gbar(gen);

        // ---- O ----
        {
            float2 rv = sgemm2(g_ht, 128, m0, g_W2t + n0, true, sm, tid);
            rv.x += g_b2[n]; rv.y += g_b2[n+1];
            if (m0 < 64) {
                size_t o = ((size_t)m*TT + t)*DD + n;
                *(float2*)&out[o] = rv;
                if (dup) *(float2*)&out[BTD + o] = rv;
            } else {
                int b = m - 64;
                float2 v = *(const float2*)&g_V[(size_t)t*NBD + (size_t)b*DD + n];
                float d0 = rv.x - v.x, d1 = rv.y - v.y;
                *(float2*)&g_diff[(size_t)b*DD + n] = make_float2(d0, d1);
                g_difft[(size_t)n*64 + b] = d0; g_difft[(size_t)(n+1)*64 + b] = d1;
                float lsv = d0*d0 + d1*d1;
                #pragma unroll
                for (int o2 = 16; o2; o2 >>= 1) lsv += __shfl_down_sync(0xffffffffu, lsv, o2);
                if ((tid & 31) == 0) red[tid >> 5] = lsv;
                __syncthreads();
                if (tid == 0) {
                    float sv = 0.f;
                    #pragma unroll
                    for (int i = 0; i < 8; i++) sv += red[i];
                    atomicAdd(&g_loss[t], sv);
                }
            }
        }
        if (t == TT-1) break;
        gbar(gen);

        // ---- D: CTAs 0-63 dpre ; CTAs 64-127 gW2 (tile 32x128) ----
        if (cta < 64) {
            float2 rv = sgemm2(g_difft, 64, m0, g_W2 + n0, false, sm, tid);
            float2 hp = *(const float2*)&g_h[(size_t)(64 + m)*DD + n];
            *(float2*)&g_dpre[(size_t)m*DD + n] =
                make_float2(hp.x > 0.f ? rv.x : 0.f, hp.y > 0.f ? rv.y : 0.f);
        } else {
            int id = cta - 64;
            int i0 = (id >> 2) * 32, j0 = (id & 3) * 128;
            float (*Ag)[36]  = (float(*)[36])sm;
            float (*Bg)[132] = (float(*)[132])(sm + 64*36);
            #pragma unroll
            for (int i = 0; i < 2; i++) {
                int e = tid + i*256; int b = e >> 3, iq = e & 7;
                *(float4*)&Ag[b][iq*4] = *(const float4*)&g_diff[(size_t)b*DD + i0 + iq*4];
            }
            #pragma unroll
            for (int i = 0; i < 8; i++) {
                int e = tid + i*256; int b = e >> 5, jq = e & 31;
                float4 v = *(const float4*)&g_h[(size_t)(64 + b)*DD + j0 + jq*4];
                v.x=fmaxf(v.x,0.f); v.y=fmaxf(v.y,0.f); v.z=fmaxf(v.z,0.f); v.w=fmaxf(v.w,0.f);
                *(float4*)&Bg[b][jq*4] = v;
            }
            __syncthreads();
            int ti = tid >> 5, tj = tid & 31;
            u64 q[4][2];
            #pragma unroll
            for (int i = 0; i < 4; i++) { q[i][0] = 0ull; q[i][1] = 0ull; }
            #pragma unroll 4
            for (int b = 0; b < 64; b++) {
                float4 av = *(const float4*)&Ag[b][ti*4];
                ulonglong2 bv = *(const ulonglong2*)&Bg[b][tj*4];
                u64 sx;
                sx = pk2(av.x,av.x); fma2(q[0][0],sx,bv.x); fma2(q[0][1],sx,bv.y);
                sx = pk2(av.y,av.y); fma2(q[1][0],sx,bv.x); fma2(q[1][1],sx,bv.y);
                sx = pk2(av.z,av.z); fma2(q[2][0],sx,bv.x); fma2(q[2][1],sx,bv.y);
                sx = pk2(av.w,av.w); fma2(q[3][0],sx,bv.x); fma2(q[3][1],sx,bv.y);
            }
            #pragma unroll
            for (int ii = 0; ii < 4; ii++) {
                float2 p0 = up2(q[ii][0]), p1 = up2(q[ii][1]);
                *(float4*)&g_gW2[(size_t)(i0 + ti*4 + ii)*DD + j0 + tj*4] =
                    make_float4(p0.x, p0.y, p1.x, p1.y);
            }
        }
        gbar(gen);
    }
}

extern "C" void kernel_launch(void* const* d_in, const int* in_sizes, int n_in,
                              void* d_out, int out_size) {
    const float* x   = (const float*)d_in[0];
    const float* WQ  = (const float*)d_in[1];
    const float* WK  = (const float*)d_in[2];
    const float* WV  = (const float*)d_in[3];
    const float* thw = (const float*)d_in[4];
    const float* thb = (const float*)d_in[5];
    const float* etw = (const float*)d_in[6];
    const float* etb = (const float*)d_in[7];
    const float* alw = (const float*)d_in[8];
    const float* alb = (const float*)d_in[9];
    const float* W1  = (const float*)d_in[10];
    const float* b1  = (const float*)d_in[11];
    const float* W2  = (const float*)d_in[12];
    const float* b2  = (const float*)d_in[13];
    float* out = (float*)d_out;
    int dup = (out_size >= 2 * BTD) ? 1 : 0;

    k_init<<<1024, 256>>>(W1, b1, W2, b2);
    k_gates<<<TT, 256>>>(x, thw, thb, etw, etb, alw, alb);
    k_qkv<<<dim3(8, 128, 3), 256>>>(x, WQ, WK, WV);
    k_scan<<<G_CTAS, 256>>>(out, dup);
}

// round 9
// speedup vs baseline: 1.7677x; 1.2618x over previous
#include <cuda_runtime.h>
#include <math.h>

#define BB 64
#define TT 128
#define DD 512
#define NBD (BB*DD)
#define BTD (BB*TT*DD)
#define G_CTAS 128
#define SCAN_SMEM 106496   /* (4096 + 2*128*68 + 5120) floats */

typedef unsigned long long u64;

__device__ float g_Qt[TT*NBD];     // [t][k][b]
__device__ float g_Kt[TT*NBD];     // [t][k][b]
__device__ float g_K [TT*NBD];     // [t][b][k]
__device__ float g_V [TT*NBD];     // [t][b][k]
__device__ float g_th[TT], g_et[TT], g_al[TT];
__device__ float g_W1[DD*DD], g_M1w[DD*DD], g_b1[DD], g_M1b[DD];
__device__ float g_W2[DD*DD], g_M2w[DD*DD], g_b2[DD], g_M2b[DD];
__device__ float g_W1t[DD*DD], g_W2t[DD*DD];   // [k][n]
__device__ float g_h[2*NBD];       // rows 0-63 q-path, 64-127 k-path
__device__ float g_ht[2*NBD];      // [n][m] (128 m per row)
__device__ float g_diff[NBD];      // [b][n]
__device__ float g_difft[NBD];     // [n][b]
__device__ float g_dpre[NBD];      // [b][n]
__device__ float g_gW2[DD*DD];
__device__ float g_loss[TT];
__device__ unsigned g_barcnt;
__device__ volatile unsigned g_bargen;

__device__ __forceinline__ u64 pk2(float x, float y){
    u64 r; asm("mov.b64 %0, {%1, %2};" : "=l"(r) : "f"(x), "f"(y)); return r;
}
__device__ __forceinline__ void fma2(u64 &c, u64 a, u64 b){
    asm("fma.rn.f32x2 %0, %1, %2, %0;" : "+l"(c) : "l"(a), "l"(b));
}
__device__ __forceinline__ u64 add2(u64 a, u64 b){
    u64 r; asm("add.rn.f32x2 %0, %1, %2;" : "=l"(r) : "l"(a), "l"(b)); return r;
}
__device__ __forceinline__ float2 up2(u64 v){
    float lo, hi; asm("mov.b64 {%0, %1}, %2;" : "=f"(lo), "=f"(hi) : "l"(v));
    return make_float2(lo, hi);
}
__device__ __forceinline__ unsigned smaddr(const void* p){
    return (unsigned)__cvta_generic_to_shared(p);
}

__device__ __forceinline__ void gbar(unsigned &gen){
    __syncthreads();
    if (threadIdx.x == 0){
        __threadfence();
        unsigned target = (gen + 1u) * (unsigned)G_CTAS;
        if (atomicAdd(&g_barcnt, 1u) + 1u == target) g_bargen = gen + 1u;
        else while (g_bargen < gen + 1u) { __nanosleep(32); }
        __threadfence();
    }
    __syncthreads();
    gen++;
}

__global__ void k_init(const float* __restrict__ W1, const float* __restrict__ b1,
                       const float* __restrict__ W2, const float* __restrict__ b2) {
    int i = blockIdx.x * 256 + threadIdx.x;
    if (i < DD*DD) {
        g_W1[i] = W1[i]; g_M1w[i] = 0.f; g_W2[i] = W2[i]; g_M2w[i] = 0.f;
        int tr = (i & 511) * 512 + (i >> 9);
        g_W1t[tr] = W1[i]; g_W2t[tr] = W2[i];
    }
    if (i < DD) { g_b1[i] = b1[i]; g_M1b[i] = 0.f; g_b2[i] = b2[i]; g_M2b[i] = 0.f; }
    if (i < TT) g_loss[i] = 0.f;
    if (i == 0) { g_barcnt = 0u; g_bargen = 0u; }
}

__global__ void k_gates(const float* __restrict__ x,
                        const float* __restrict__ thw, const float* __restrict__ thb,
                        const float* __restrict__ etw, const float* __restrict__ etb,
                        const float* __restrict__ alw, const float* __restrict__ alb) {
    int t = blockIdx.x, tid = threadIdx.x, lane = tid & 31, warp = tid >> 5;
    __shared__ float red[8];
    for (int g = 0; g < 3; g++) {
        const float* w = (g == 0) ? thw : ((g == 1) ? etw : alw);
        float b0 = (g == 0) ? thb[0] : ((g == 1) ? etb[0] : alb[0]);
        float acc = 0.f;
        for (int bi = warp; bi < BB; bi += 8) {
            const float* xr = x + ((size_t)bi * TT + t) * DD;
            float s = 0.f;
            for (int k = lane; k < DD; k += 32) s += xr[k] * w[k];
            #pragma unroll
            for (int o = 16; o; o >>= 1) s += __shfl_down_sync(0xffffffffu, s, o);
            if (lane == 0) acc += 1.f / (1.f + expf(-(s + b0)));
        }
        if (lane == 0) red[warp] = acc;
        __syncthreads();
        if (tid == 0) {
            float s = 0.f;
            #pragma unroll
            for (int i = 0; i < 8; i++) s += red[i];
            s *= (1.f / (float)BB);
            if (g == 0) g_th[t] = s; else if (g == 1) g_et[t] = s; else g_al[t] = s;
        }
        __syncthreads();
    }
}

__global__ __launch_bounds__(256) void k_qkv(const float* __restrict__ x,
                       const float* __restrict__ WQ, const float* __restrict__ WK,
                       const float* __restrict__ WV) {
    __shared__ float As[64][33], Bsh[64][33];
    int n0 = blockIdx.x * 64, m0 = blockIdx.y * 64, z = blockIdx.z;
    const float* W = (z == 0) ? WQ : ((z == 1) ? WK : WV);
    int tid = threadIdx.x;
    int r0 = (tid >> 4) * 4, c0 = (tid & 15) * 4;
    float acc[4][4];
    #pragma unroll
    for (int i = 0; i < 4; i++)
        #pragma unroll
        for (int j = 0; j < 4; j++) acc[i][j] = 0.f;
    for (int kb = 0; kb < 16; kb++) {
        #pragma unroll
        for (int i = 0; i < 2; i++) {
            int e = tid + i*256;
            int row = e >> 3, kq = e & 7;
            int m = m0 + row;
            float4 xv = *(const float4*)&x[((size_t)(m & 63)*TT + (m >> 6))*DD + kb*32 + kq*4];
            As[row][4*kq+0]=xv.x; As[row][4*kq+1]=xv.y; As[row][4*kq+2]=xv.z; As[row][4*kq+3]=xv.w;
            float4 wv = *(const float4*)&W[(size_t)(n0 + row)*DD + kb*32 + kq*4];
            Bsh[row][4*kq+0]=wv.x; Bsh[row][4*kq+1]=wv.y; Bsh[row][4*kq+2]=wv.z; Bsh[row][4*kq+3]=wv.w;
        }
        __syncthreads();
        #pragma unroll 4
        for (int kk = 0; kk < 32; kk++) {
            float a0 = As[r0+0][kk], a1 = As[r0+1][kk], a2 = As[r0+2][kk], a3 = As[r0+3][kk];
            float b0 = Bsh[c0+0][kk], b1 = Bsh[c0+1][kk], b2 = Bsh[c0+2][kk], b3 = Bsh[c0+3][kk];
            acc[0][0]+=a0*b0; acc[0][1]+=a0*b1; acc[0][2]+=a0*b2; acc[0][3]+=a0*b3;
            acc[1][0]+=a1*b0; acc[1][1]+=a1*b1; acc[1][2]+=a1*b2; acc[1][3]+=a1*b3;
            acc[2][0]+=a2*b0; acc[2][1]+=a2*b1; acc[2][2]+=a2*b2; acc[2][3]+=a2*b3;
            acc[3][0]+=a3*b0; acc[3][1]+=a3*b1; acc[3][2]+=a3*b2; acc[3][3]+=a3*b3;
        }
        __syncthreads();
    }
    int tl = m0 >> 6;
    #pragma unroll
    for (int i = 0; i < 4; i++) {
        int mrow = m0 + r0 + i, b = mrow & 63;
        float4 v = make_float4(acc[i][0], acc[i][1], acc[i][2], acc[i][3]);
        if (z == 2) { *(float4*)&g_V[(size_t)mrow*DD + n0 + c0] = v; }
        else {
            float* Ot = (z == 0) ? g_Qt : g_Kt;
            if (z == 1) *(float4*)&g_K[(size_t)mrow*DD + n0 + c0] = v;
            #pragma unroll
            for (int j = 0; j < 4; j++)
                Ot[(size_t)tl*NBD + (size_t)(n0 + c0 + j)*64 + b] = acc[i][j];
        }
    }
}

// C[8x64] = A(k-major [512][Ms], rows moff..+8) @ Bk(k-major rows, stride DD, 64 cols)
// 512 threads, split-K x8, cp.async double-buffered B (4 chunks of 128 k).
// Result valid for tid<256 at (m=tid>>5, n=2*(tid&31)).
__device__ __forceinline__ float2 sgemm3(const float* __restrict__ Akt, int Ms, int moff,
                                         const float* __restrict__ Bk, bool reluA,
                                         float* sm, int tid) {
    float* At   = sm;            // [k*8+m], 4096 floats
    float* Bs   = sm + 4096;     // 2 x [128][68]
    float* sred = sm + 21504;    // 512*10
    #pragma unroll
    for (int c = 0; c < 2; c++) {
        #pragma unroll
        for (int i = 0; i < 4; i++) {
            int e = tid + i*512; int kq = e >> 4, nq = e & 15;
            unsigned dst = smaddr(&Bs[c*8704 + kq*68 + nq*4]);
            const float* src = &Bk[(size_t)(c*128 + kq)*DD + nq*4];
            asm volatile("cp.async.ca.shared.global [%0], [%1], 16;" :: "r"(dst), "l"(src));
        }
        asm volatile("cp.async.commit_group;");
    }
    #pragma unroll
    for (int i = 0; i < 2; i++) {
        int e = tid + i*512; int k = e >> 1, mq = (e & 1)*4;
        float4 v = *(const float4*)&Akt[(size_t)k*Ms + moff + mq];
        if (reluA) { v.x=fmaxf(v.x,0.f); v.y=fmaxf(v.y,0.f); v.z=fmaxf(v.z,0.f); v.w=fmaxf(v.w,0.f); }
        *(float4*)&At[k*8 + mq] = v;
    }
    int ks = tid >> 6, rq = (tid >> 5) & 1, cv = tid & 31;
    u64 ac0=0ull, ac1=0ull, ac2=0ull, ac3=0ull;
    for (int c = 0; c < 4; c++) {
        asm volatile("cp.async.wait_group 1;");
        __syncthreads();
        const float* ap = At + (c*128 + ks*16)*8 + rq*4;
        const float* bp = Bs + (c&1)*8704 + (ks*16)*68 + 2*cv;
        #pragma unroll
        for (int kk = 0; kk < 16; kk++) {
            float4 a = *(const float4*)(ap + kk*8);
            u64 b = *(const u64*)(bp + kk*68);
            fma2(ac0, pk2(a.x,a.x), b);
            fma2(ac1, pk2(a.y,a.y), b);
            fma2(ac2, pk2(a.z,a.z), b);
            fma2(ac3, pk2(a.w,a.w), b);
        }
        __syncthreads();
        if (c < 2) {
            #pragma unroll
            for (int i = 0; i < 4; i++) {
                int e = tid + i*512; int kq = e >> 4, nq = e & 15;
                unsigned dst = smaddr(&Bs[(c&1)*8704 + kq*68 + nq*4]);
                const float* src = &Bk[(size_t)((c+2)*128 + kq)*DD + nq*4];
                asm volatile("cp.async.ca.shared.global [%0], [%1], 16;" :: "r"(dst), "l"(src));
            }
        }
        asm volatile("cp.async.commit_group;");
    }
    u64* rp = (u64*)&sred[tid*10];
    rp[0]=ac0; rp[1]=ac1; rp[2]=ac2; rp[3]=ac3;
    __syncthreads();
    float2 T = make_float2(0.f, 0.f);
    if (tid < 256) {
        int m = tid >> 5, c2 = tid & 31, rq2 = m >> 2, ri = m & 3;
        u64 acc = 0ull;
        #pragma unroll
        for (int k2 = 0; k2 < 8; k2++)
            acc = add2(acc, *(const u64*)&sred[((k2*2 + rq2)*32 + c2)*10 + ri*2]);
        T = up2(acc);
    }
    return T;
}

__global__ __launch_bounds__(512, 1) void k_scan(float* __restrict__ out, int dup) {
    extern __shared__ __align__(16) float sm[];
    __shared__ float red[16];
    int cta = blockIdx.x, tid = threadIdx.x;
    unsigned gen = 0;

    for (int t = 0; t < TT; t++) {
        // ---- U: fused gW1 + all weight/bias updates (grads of t-1) ----
        if (t > 0) {
            float th = g_th[t-1], et = g_et[t-1], al = g_al[t-1];
            float ls = g_loss[t-1] * (1.f/(float)NBD);
            float pt = (ls >= 1e-10f && ls <= 1e10f) ? 1.f : 0.f;
            float s  = th * pt * (2.f/(float)NBD);
            float oa = 1.f - al;
            int i0 = (cta >> 3) * 32, j0 = (cta & 7) * 64;
            float (*sDp)[36] = (float(*)[36])sm;
            float (*sK)[68]  = (float(*)[68])(sm + 64*36);
            { int e = tid; int b = e >> 3, iq = e & 7;
              *(float4*)&sDp[b][iq*4] = *(const float4*)&g_dpre[(size_t)b*DD + i0 + iq*4]; }
            const float* Kt = g_K + (size_t)(t-1)*NBD;
            #pragma unroll
            for (int i = 0; i < 2; i++) {
                int e = tid + i*512; int b = e >> 4, jq = e & 15;
                *(float4*)&sK[b][jq*4] = *(const float4*)&Kt[(size_t)b*DD + j0 + jq*4];
            }
            __syncthreads();
            int ti = tid >> 4, tj = tid & 15;
            u64 a0 = 0ull, a1 = 0ull;
            #pragma unroll 8
            for (int b = 0; b < 64; b++) {
                float av = sDp[b][ti];
                ulonglong2 bv = *(const ulonglong2*)&sK[b][tj*4];
                u64 sx = pk2(av, av);
                fma2(a0, sx, bv.x); fma2(a1, sx, bv.y);
            }
            float2 p0 = up2(a0), p1 = up2(a1);
            float gr[4] = {p0.x, p0.y, p1.x, p1.y};
            int iw = i0 + ti, jw = j0 + tj*4;
            size_t idx = (size_t)iw*DD + jw;
            {
                float4 mm = *(const float4*)&g_M1w[idx];
                float4 ww = *(const float4*)&g_W1[idx];
                mm.x = et*mm.x - s*gr[0]; ww.x = oa*ww.x + mm.x;
                mm.y = et*mm.y - s*gr[1]; ww.y = oa*ww.y + mm.y;
                mm.z = et*mm.z - s*gr[2]; ww.z = oa*ww.z + mm.z;
                mm.w = et*mm.w - s*gr[3]; ww.w = oa*ww.w + mm.w;
                *(float4*)&g_M1w[idx] = mm; *(float4*)&g_W1[idx] = ww;
                g_W1t[(size_t)(jw+0)*DD + iw] = ww.x; g_W1t[(size_t)(jw+1)*DD + iw] = ww.y;
                g_W1t[(size_t)(jw+2)*DD + iw] = ww.z; g_W1t[(size_t)(jw+3)*DD + iw] = ww.w;
            }
            {
                float4 gg = *(const float4*)&g_gW2[idx];
                float4 mm = *(const float4*)&g_M2w[idx];
                float4 ww = *(const float4*)&g_W2[idx];
                mm.x = et*mm.x - s*gg.x; ww.x = oa*ww.x + mm.x;
                mm.y = et*mm.y - s*gg.y; ww.y = oa*ww.y + mm.y;
                mm.z = et*mm.z - s*gg.z; ww.z = oa*ww.z + mm.z;
                mm.w = et*mm.w - s*gg.w; ww.w = oa*ww.w + mm.w;
                *(float4*)&g_M2w[idx] = mm; *(float4*)&g_W2[idx] = ww;
                g_W2t[(size_t)(jw+0)*DD + iw] = ww.x; g_W2t[(size_t)(jw+1)*DD + iw] = ww.y;
                g_W2t[(size_t)(jw+2)*DD + iw] = ww.z; g_W2t[(size_t)(jw+3)*DD + iw] = ww.w;
            }
            if ((cta & 7) == 0 && tid < 64) {
                if (tid < 32) {
                    int c = i0 + tid; float g = 0.f;
                    #pragma unroll 8
                    for (int b = 0; b < 64; b++) g += sDp[b][tid];
                    float m = et*g_M1b[c] - s*g; g_M1b[c] = m; g_b1[c] = oa*g_b1[c] + m;
                } else {
                    int c = i0 + tid - 32; float g = 0.f;
                    const float* dp = g_difft + (size_t)c*64;
                    #pragma unroll
                    for (int b = 0; b < 64; b += 4) {
                        float4 v = *(const float4*)&dp[b];
                        g += v.x + v.y + v.z + v.w;
                    }
                    float m = et*g_M2b[c] - s*g; g_M2b[c] = m; g_b2[c] = oa*g_b2[c] + m;
                }
            }
            gbar(gen);
        }

        int m0 = (cta >> 3) * 8, n0 = (cta & 7) * 64;
        int r = tid >> 5, c2 = (tid & 31) * 2;
        int m = m0 + r, n = n0 + c2;

        // ---- H ----
        {
            const float* Akt = (m0 < 64) ? (g_Qt + (size_t)t*NBD) : (g_Kt + (size_t)t*NBD);
            int moff = (m0 < 64) ? m0 : (m0 - 64);
            float2 rv = sgemm3(Akt, 64, moff, g_W1t + n0, false, sm, tid);
            if (tid < 256) {
                rv.x += g_b1[n]; rv.y += g_b1[n+1];
                *(float2*)&g_h[(size_t)m*DD + n] = rv;
                g_ht[(size_t)n*128 + m] = rv.x; g_ht[(size_t)(n+1)*128 + m] = rv.y;
            }
        }
        gbar(gen);

        // ---- O ----
        {
            float2 rv = sgemm3(g_ht, 128, m0, g_W2t + n0, true, sm, tid);
            float lsv = 0.f;
            if (tid < 256) {
                rv.x += g_b2[n]; rv.y += g_b2[n+1];
                if (m0 < 64) {
                    size_t o = ((size_t)m*TT + t)*DD + n;
                    *(float2*)&out[o] = rv;
                    if (dup) *(float2*)&out[BTD + o] = rv;
                } else {
                    int b = m - 64;
                    float2 v = *(const float2*)&g_V[(size_t)t*NBD + (size_t)b*DD + n];
                    float d0 = rv.x - v.x, d1 = rv.y - v.y;
                    *(float2*)&g_diff[(size_t)b*DD + n] = make_float2(d0, d1);
                    g_difft[(size_t)n*64 + b] = d0; g_difft[(size_t)(n+1)*64 + b] = d1;
                    lsv = d0*d0 + d1*d1;
                }
            }
            if (m0 >= 64) {
                #pragma unroll
                for (int o2 = 16; o2; o2 >>= 1) lsv += __shfl_down_sync(0xffffffffu, lsv, o2);
                if ((tid & 31) == 0) red[tid >> 5] = lsv;
                __syncthreads();
                if (tid == 0) {
                    float sv = 0.f;
                    #pragma unroll
                    for (int i = 0; i < 16; i++) sv += red[i];
                    atomicAdd(&g_loss[t], sv);
                }
            }
        }
        if (t == TT-1) break;
        gbar(gen);

        // ---- D: CTAs 0-63 dpre ; CTAs 64-127 gW2 (32x128 tiles) ----
        if (cta < 64) {
            float2 rv = sgemm3(g_difft, 64, m0, g_W2 + n0, false, sm, tid);
            if (tid < 256) {
                float2 hp = *(const float2*)&g_h[(size_t)(64 + m)*DD + n];
                *(float2*)&g_dpre[(size_t)m*DD + n] =
                    make_float2(hp.x > 0.f ? rv.x : 0.f, hp.y > 0.f ? rv.y : 0.f);
            }
        } else {
            int id = cta - 64;
            int i0 = (id >> 2) * 32, j0 = (id & 3) * 128;
            float (*Ag)[36]  = (float(*)[36])sm;
            float (*Bg)[132] = (float(*)[132])(sm + 64*36);
            { int e = tid; int b = e >> 3, iq = e & 7;
              *(float4*)&Ag[b][iq*4] = *(const float4*)&g_diff[(size_t)b*DD + i0 + iq*4]; }
            #pragma unroll
            for (int i = 0; i < 4; i++) {
                int e = tid + i*512; int b = e >> 5, jq = e & 31;
                float4 v = *(const float4*)&g_h[(size_t)(64 + b)*DD + j0 + jq*4];
                v.x=fmaxf(v.x,0.f); v.y=fmaxf(v.y,0.f); v.z=fmaxf(v.z,0.f); v.w=fmaxf(v.w,0.f);
                *(float4*)&Bg[b][jq*4] = v;
            }
            __syncthreads();
            int ti = tid >> 5, tj = tid & 31;
            u64 q00=0ull, q01=0ull, q10=0ull, q11=0ull;
            #pragma unroll 8
            for (int b = 0; b < 64; b++) {
                float2 av = *(const float2*)&Ag[b][ti*2];
                ulonglong2 bv = *(const ulonglong2*)&Bg[b][tj*4];
                u64 s0 = pk2(av.x,av.x), s1 = pk2(av.y,av.y);
                fma2(q00,s0,bv.x); fma2(q01,s0,bv.y);
                fma2(q10,s1,bv.x); fma2(q11,s1,bv.y);
            }
            float2 p0 = up2(q00), p1 = up2(q01), p2 = up2(q10), p3 = up2(q11);
            *(float4*)&g_gW2[(size_t)(i0 + ti*2    )*DD + j0 + tj*4] = make_float4(p0.x,p0.y,p1.x,p1.y);
            *(float4*)&g_gW2[(size_t)(i0 + ti*2 + 1)*DD + j0 + tj*4] = make_float4(p2.x,p2.y,p3.x,p3.y);
        }
        gbar(gen);
    }
}

extern "C" void kernel_launch(void* const* d_in, const int* in_sizes, int n_in,
                              void* d_out, int out_size) {
    const float* x   = (const float*)d_in[0];
    const float* WQ  = (const float*)d_in[1];
    const float* WK  = (const float*)d_in[2];
    const float* WV  = (const float*)d_in[3];
    const float* thw = (const float*)d_in[4];
    const float* thb = (const float*)d_in[5];
    const float* etw = (const float*)d_in[6];
    const float* etb = (const float*)d_in[7];
    const float* alw = (const float*)d_in[8];
    const float* alb = (const float*)d_in[9];
    const float* W1  = (const float*)d_in[10];
    const float* b1  = (const float*)d_in[11];
    const float* W2  = (const float*)d_in[12];
    const float* b2  = (const float*)d_in[13];
    float* out = (float*)d_out;
    int dup = (out_size >= 2 * BTD) ? 1 : 0;

    cudaFuncSetAttribute(k_scan, cudaFuncAttributeMaxDynamicSharedMemorySize, SCAN_SMEM);
    k_init<<<1024, 256>>>(W1, b1, W2, b2);
    k_gates<<<TT, 256>>>(x, thw, thb, etw, etb, alw, alb);
    k_qkv<<<dim3(8, 128, 3), 256>>>(x, WQ, WK, WV);
    k_scan<<<G_CTAS, 512, SCAN_SMEM>>>(out, dup);
}

// round 10
// speedup vs baseline: 1.7793x; 1.0065x over previous
#include <cuda_runtime.h>
#include <math.h>

#define BB 64
#define TT 128
#define DD 512
#define NBD (BB*DD)
#define BTD (BB*TT*DD)
#define G_CTAS 128
#define SCAN_SMEM 106496

typedef unsigned long long u64;

__device__ float g_Qt[TT*NBD];     // [t][k][b]
__device__ float g_Kt[TT*NBD];     // [t][k][b]
__device__ float g_K [TT*NBD];     // [t][b][k]
__device__ float g_V [TT*NBD];     // [t][b][k]
__device__ float g_th[TT], g_et[TT], g_al[TT];
__device__ float g_W1[DD*DD], g_M1w[DD*DD], g_b1[DD], g_M1b[DD];
__device__ float g_W2p[2][DD*DD];  // ping-pong row-major W2 (read parity t&1)
__device__ float g_M2w[DD*DD], g_b2[DD], g_M2b[DD];
__device__ float g_W1t[DD*DD], g_W2t[DD*DD];   // [k][n]
__device__ float g_h[2*NBD];
__device__ float g_ht[2*NBD];      // [n][m]
__device__ float g_diff[NBD];      // [b][n]
__device__ float g_difft[NBD];     // [n][b]
__device__ float g_dpre[NBD];      // [b][n]
__device__ float g_loss[TT];
__device__ unsigned g_barcnt;
__device__ unsigned g_bargen;

__device__ __forceinline__ u64 pk2(float x, float y){
    u64 r; asm("mov.b64 %0, {%1, %2};" : "=l"(r) : "f"(x), "f"(y)); return r;
}
__device__ __forceinline__ void fma2(u64 &c, u64 a, u64 b){
    asm("fma.rn.f32x2 %0, %1, %2, %0;" : "+l"(c) : "l"(a), "l"(b));
}
__device__ __forceinline__ u64 add2(u64 a, u64 b){
    u64 r; asm("add.rn.f32x2 %0, %1, %2;" : "=l"(r) : "l"(a), "l"(b)); return r;
}
__device__ __forceinline__ float2 up2(u64 v){
    float lo, hi; asm("mov.b64 {%0, %1}, %2;" : "=f"(lo), "=f"(hi) : "l"(v));
    return make_float2(lo, hi);
}
__device__ __forceinline__ unsigned smaddr(const void* p){
    return (unsigned)__cvta_generic_to_shared(p);
}

// CG-style grid barrier: acq_rel arrival, release publish, acquire spin.
__device__ __forceinline__ void gbar(unsigned &gen){
    __syncthreads();
    if (threadIdx.x == 0){
        unsigned target = (gen + 1u) * (unsigned)G_CTAS;
        unsigned prev;
        asm volatile("atom.acq_rel.gpu.global.add.u32 %0, [%1], 1;"
                     : "=r"(prev) : "l"(&g_barcnt) : "memory");
        if (prev + 1u == target){
            asm volatile("st.release.gpu.global.u32 [%0], %1;"
                         :: "l"(&g_bargen), "r"(gen + 1u) : "memory");
        } else {
            unsigned v;
            do {
                asm volatile("ld.acquire.gpu.global.u32 %0, [%1];"
                             : "=r"(v) : "l"(&g_bargen) : "memory");
            } while (v < gen + 1u);
        }
    }
    __syncthreads();
    gen++;
}

__global__ void k_init(const float* __restrict__ W1, const float* __restrict__ b1,
                       const float* __restrict__ W2, const float* __restrict__ b2) {
    int i = blockIdx.x * 256 + threadIdx.x;
    if (i < DD*DD) {
        g_W1[i] = W1[i]; g_M1w[i] = 0.f; g_W2p[0][i] = W2[i]; g_M2w[i] = 0.f;
        int tr = (i & 511) * 512 + (i >> 9);
        g_W1t[tr] = W1[i]; g_W2t[tr] = W2[i];
    }
    if (i < DD) { g_b1[i] = b1[i]; g_M1b[i] = 0.f; g_b2[i] = b2[i]; g_M2b[i] = 0.f; }
    if (i < TT) g_loss[i] = 0.f;
    if (i == 0) { g_barcnt = 0u; g_bargen = 0u; }
}

__global__ void k_gates(const float* __restrict__ x,
                        const float* __restrict__ thw, const float* __restrict__ thb,
                        const float* __restrict__ etw, const float* __restrict__ etb,
                        const float* __restrict__ alw, const float* __restrict__ alb) {
    int t = blockIdx.x, tid = threadIdx.x, lane = tid & 31, warp = tid >> 5;
    __shared__ float red[8];
    for (int g = 0; g < 3; g++) {
        const float* w = (g == 0) ? thw : ((g == 1) ? etw : alw);
        float b0 = (g == 0) ? thb[0] : ((g == 1) ? etb[0] : alb[0]);
        float acc = 0.f;
        for (int bi = warp; bi < BB; bi += 8) {
            const float* xr = x + ((size_t)bi * TT + t) * DD;
            float s = 0.f;
            for (int k = lane; k < DD; k += 32) s += xr[k] * w[k];
            #pragma unroll
            for (int o = 16; o; o >>= 1) s += __shfl_down_sync(0xffffffffu, s, o);
            if (lane == 0) acc += 1.f / (1.f + expf(-(s + b0)));
        }
        if (lane == 0) red[warp] = acc;
        __syncthreads();
        if (tid == 0) {
            float s = 0.f;
            #pragma unroll
            for (int i = 0; i < 8; i++) s += red[i];
            s *= (1.f / (float)BB);
            if (g == 0) g_th[t] = s; else if (g == 1) g_et[t] = s; else g_al[t] = s;
        }
        __syncthreads();
    }
}

__global__ __launch_bounds__(256) void k_qkv(const float* __restrict__ x,
                       const float* __restrict__ WQ, const float* __restrict__ WK,
                       const float* __restrict__ WV) {
    __shared__ float As[64][33];
    __shared__ float Bsk[32][68];   // [k][n]
    int n0 = blockIdx.x * 64, m0 = blockIdx.y * 64, z = blockIdx.z;
    const float* W = (z == 0) ? WQ : ((z == 1) ? WK : WV);
    int tid = threadIdx.x;
    int r0 = (tid >> 4) * 4, c0 = (tid & 15) * 4;
    u64 acc[4][2];
    #pragma unroll
    for (int i = 0; i < 4; i++) { acc[i][0] = 0ull; acc[i][1] = 0ull; }
    for (int kb = 0; kb < 16; kb++) {
        #pragma unroll
        for (int i = 0; i < 2; i++) {
            int e = tid + i*256; int row = e >> 3, kq = e & 7;
            int m = m0 + row;
            float4 xv = *(const float4*)&x[((size_t)(m & 63)*TT + (m >> 6))*DD + kb*32 + kq*4];
            As[row][4*kq+0]=xv.x; As[row][4*kq+1]=xv.y; As[row][4*kq+2]=xv.z; As[row][4*kq+3]=xv.w;
            float4 wv = *(const float4*)&W[(size_t)(n0 + row)*DD + kb*32 + kq*4];
            Bsk[4*kq+0][row]=wv.x; Bsk[4*kq+1][row]=wv.y; Bsk[4*kq+2][row]=wv.z; Bsk[4*kq+3][row]=wv.w;
        }
        __syncthreads();
        #pragma unroll 8
        for (int kk = 0; kk < 32; kk++) {
            float a0 = As[r0+0][kk], a1 = As[r0+1][kk], a2 = As[r0+2][kk], a3 = As[r0+3][kk];
            ulonglong2 bb = *(const ulonglong2*)&Bsk[kk][c0];
            u64 sx;
            sx = pk2(a0,a0); fma2(acc[0][0],sx,bb.x); fma2(acc[0][1],sx,bb.y);
            sx = pk2(a1,a1); fma2(acc[1][0],sx,bb.x); fma2(acc[1][1],sx,bb.y);
            sx = pk2(a2,a2); fma2(acc[2][0],sx,bb.x); fma2(acc[2][1],sx,bb.y);
            sx = pk2(a3,a3); fma2(acc[3][0],sx,bb.x); fma2(acc[3][1],sx,bb.y);
        }
        __syncthreads();
    }
    int tl = m0 >> 6;
    #pragma unroll
    for (int i = 0; i < 4; i++) {
        float2 p0 = up2(acc[i][0]), p1 = up2(acc[i][1]);
        int mrow = m0 + r0 + i, b = mrow & 63;
        float4 v = make_float4(p0.x, p0.y, p1.x, p1.y);
        if (z == 2) { *(float4*)&g_V[(size_t)mrow*DD + n0 + c0] = v; }
        else {
            float* Ot = (z == 0) ? g_Qt : g_Kt;
            if (z == 1) *(float4*)&g_K[(size_t)mrow*DD + n0 + c0] = v;
            Ot[(size_t)tl*NBD + (size_t)(n0 + c0 + 0)*64 + b] = p0.x;
            Ot[(size_t)tl*NBD + (size_t)(n0 + c0 + 1)*64 + b] = p0.y;
            Ot[(size_t)tl*NBD + (size_t)(n0 + c0 + 2)*64 + b] = p1.x;
            Ot[(size_t)tl*NBD + (size_t)(n0 + c0 + 3)*64 + b] = p1.y;
        }
    }
}

// C[8x64] = A(k-major [512][Ms], rows moff..+8) @ Bk(k-major rows, stride DD)
// 512 threads, split-K x8, cp.async double-buffered B. Result for tid<256.
__device__ __forceinline__ float2 sgemm3(const float* __restrict__ Akt, int Ms, int moff,
                                         const float* __restrict__ Bk, bool reluA,
                                         float* sm, int tid) {
    float* At   = sm;            // 4096
    float* Bs   = sm + 4096;     // 2 x [128][68]
    float* sred = sm + 21504;    // 512*10
    #pragma unroll
    for (int c = 0; c < 2; c++) {
        #pragma unroll
        for (int i = 0; i < 4; i++) {
            int e = tid + i*512; int kq = e >> 4, nq = e & 15;
            unsigned dst = smaddr(&Bs[c*8704 + kq*68 + nq*4]);
            const float* src = &Bk[(size_t)(c*128 + kq)*DD + nq*4];
            asm volatile("cp.async.ca.shared.global [%0], [%1], 16;" :: "r"(dst), "l"(src));
        }
        asm volatile("cp.async.commit_group;");
    }
    #pragma unroll
    for (int i = 0; i < 2; i++) {
        int e = tid + i*512; int k = e >> 1, mq = (e & 1)*4;
        float4 v = *(const float4*)&Akt[(size_t)k*Ms + moff + mq];
        if (reluA) { v.x=fmaxf(v.x,0.f); v.y=fmaxf(v.y,0.f); v.z=fmaxf(v.z,0.f); v.w=fmaxf(v.w,0.f); }
        *(float4*)&At[k*8 + mq] = v;
    }
    int ks = tid >> 6, rq = (tid >> 5) & 1, cv = tid & 31;
    u64 ac0=0ull, ac1=0ull, ac2=0ull, ac3=0ull;
    for (int c = 0; c < 4; c++) {
        asm volatile("cp.async.wait_group 1;");
        __syncthreads();
        const float* ap = At + (c*128 + ks*16)*8 + rq*4;
        const float* bp = Bs + (c&1)*8704 + (ks*16)*68 + 2*cv;
        #pragma unroll
        for (int kk = 0; kk < 16; kk++) {
            float4 a = *(const float4*)(ap + kk*8);
            u64 b = *(const u64*)(bp + kk*68);
            fma2(ac0, pk2(a.x,a.x), b);
            fma2(ac1, pk2(a.y,a.y), b);
            fma2(ac2, pk2(a.z,a.z), b);
            fma2(ac3, pk2(a.w,a.w), b);
        }
        __syncthreads();
        if (c < 2) {
            #pragma unroll
            for (int i = 0; i < 4; i++) {
                int e = tid + i*512; int kq = e >> 4, nq = e & 15;
                unsigned dst = smaddr(&Bs[(c&1)*8704 + kq*68 + nq*4]);
                const float* src = &Bk[(size_t)((c+2)*128 + kq)*DD + nq*4];
                asm volatile("cp.async.ca.shared.global [%0], [%1], 16;" :: "r"(dst), "l"(src));
            }
        }
        asm volatile("cp.async.commit_group;");
    }
    u64* rp = (u64*)&sred[tid*10];
    rp[0]=ac0; rp[1]=ac1; rp[2]=ac2; rp[3]=ac3;
    __syncthreads();
    float2 T = make_float2(0.f, 0.f);
    if (tid < 256) {
        int m = tid >> 5, c2 = tid & 31, rq2 = m >> 2, ri = m & 3;
        u64 acc = 0ull;
        #pragma unroll
        for (int k2 = 0; k2 < 8; k2++)
            acc = add2(acc, *(const u64*)&sred[((k2*2 + rq2)*32 + c2)*10 + ri*2]);
        T = up2(acc);
    }
    return T;
}

__global__ __launch_bounds__(512, 1) void k_scan(float* __restrict__ out, int dup) {
    extern __shared__ __align__(16) float sm[];
    __shared__ float red[16];
    int cta = blockIdx.x, tid = threadIdx.x;
    unsigned gen = 0;

    for (int t = 0; t < TT; t++) {
        // ---- U: gW1 + W1/b1 update (grads of t-1; W2 handled in D of t-1) ----
        if (t > 0) {
            float th = g_th[t-1], et = g_et[t-1], al = g_al[t-1];
            float ls = g_loss[t-1] * (1.f/(float)NBD);
            float pt = (ls >= 1e-10f && ls <= 1e10f) ? 1.f : 0.f;
            float s  = th * pt * (2.f/(float)NBD);
            float oa = 1.f - al;
            int i0 = (cta >> 3) * 32, j0 = (cta & 7) * 64;
            float (*sDp)[36] = (float(*)[36])sm;
            float (*sK)[68]  = (float(*)[68])(sm + 64*36);
            { int e = tid; int b = e >> 3, iq = e & 7;
              *(float4*)&sDp[b][iq*4] = *(const float4*)&g_dpre[(size_t)b*DD + i0 + iq*4]; }
            const float* Kt = g_K + (size_t)(t-1)*NBD;
            #pragma unroll
            for (int i = 0; i < 2; i++) {
                int e = tid + i*512; int b = e >> 4, jq = e & 15;
                *(float4*)&sK[b][jq*4] = *(const float4*)&Kt[(size_t)b*DD + j0 + jq*4];
            }
            __syncthreads();
            int ti = tid >> 4, tj = tid & 15;
            u64 a0 = 0ull, a1 = 0ull;
            #pragma unroll 8
            for (int b = 0; b < 64; b++) {
                float av = sDp[b][ti];
                ulonglong2 bv = *(const ulonglong2*)&sK[b][tj*4];
                u64 sx = pk2(av, av);
                fma2(a0, sx, bv.x); fma2(a1, sx, bv.y);
            }
            float2 p0 = up2(a0), p1 = up2(a1);
            int iw = i0 + ti, jw = j0 + tj*4;
            size_t idx = (size_t)iw*DD + jw;
            float4 mm = *(const float4*)&g_M1w[idx];
            float4 ww = *(const float4*)&g_W1[idx];
            mm.x = et*mm.x - s*p0.x; ww.x = oa*ww.x + mm.x;
            mm.y = et*mm.y - s*p0.y; ww.y = oa*ww.y + mm.y;
            mm.z = et*mm.z - s*p1.x; ww.z = oa*ww.z + mm.z;
            mm.w = et*mm.w - s*p1.y; ww.w = oa*ww.w + mm.w;
            *(float4*)&g_M1w[idx] = mm; *(float4*)&g_W1[idx] = ww;
            g_W1t[(size_t)(jw+0)*DD + iw] = ww.x; g_W1t[(size_t)(jw+1)*DD + iw] = ww.y;
            g_W1t[(size_t)(jw+2)*DD + iw] = ww.z; g_W1t[(size_t)(jw+3)*DD + iw] = ww.w;
            if ((cta & 7) == 0 && tid < 32) {
                int c = i0 + tid; float g = 0.f;
                #pragma unroll 8
                for (int b = 0; b < 64; b++) g += sDp[b][tid];
                float m = et*g_M1b[c] - s*g; g_M1b[c] = m; g_b1[c] = oa*g_b1[c] + m;
            }
            gbar(gen);
        }

        int m0 = (cta >> 3) * 8, n0 = (cta & 7) * 64;
        int r = tid >> 5, c2 = (tid & 31) * 2;
        int m = m0 + r, n = n0 + c2;

        // ---- H ----
        {
            const float* Akt = (m0 < 64) ? (g_Qt + (size_t)t*NBD) : (g_Kt + (size_t)t*NBD);
            int moff = (m0 < 64) ? m0 : (m0 - 64);
            float2 rv = sgemm3(Akt, 64, moff, g_W1t + n0, false, sm, tid);
            if (tid < 256) {
                rv.x += g_b1[n]; rv.y += g_b1[n+1];
                *(float2*)&g_h[(size_t)m*DD + n] = rv;
                g_ht[(size_t)n*128 + m] = rv.x; g_ht[(size_t)(n+1)*128 + m] = rv.y;
            }
        }
        gbar(gen);

        // ---- O ----
        {
            float2 rv = sgemm3(g_ht, 128, m0, g_W2t + n0, true, sm, tid);
            float lsv = 0.f;
            if (tid < 256) {
                rv.x += g_b2[n]; rv.y += g_b2[n+1];
                if (m0 < 64) {
                    size_t o = ((size_t)m*TT + t)*DD + n;
                    *(float2*)&out[o] = rv;
                    if (dup) *(float2*)&out[BTD + o] = rv;
                } else {
                    int b = m - 64;
                    float2 v = *(const float2*)&g_V[(size_t)t*NBD + (size_t)b*DD + n];
                    float d0 = rv.x - v.x, d1 = rv.y - v.y;
                    *(float2*)&g_diff[(size_t)b*DD + n] = make_float2(d0, d1);
                    g_difft[(size_t)n*64 + b] = d0; g_difft[(size_t)(n+1)*64 + b] = d1;
                    lsv = d0*d0 + d1*d1;
                }
            }
            if (m0 >= 64) {
                #pragma unroll
                for (int o2 = 16; o2; o2 >>= 1) lsv += __shfl_down_sync(0xffffffffu, lsv, o2);
                if ((tid & 31) == 0) red[tid >> 5] = lsv;
                __syncthreads();
                if (tid == 0) {
                    float sv = 0.f;
                    #pragma unroll
                    for (int i = 0; i < 16; i++) sv += red[i];
                    atomicAdd(&g_loss[t], sv);
                }
            }
        }
        if (t == TT-1) break;
        gbar(gen);

        // ---- D: CTAs 0-63 dpre ; CTAs 64-127 gW2 + fused W2/b2 update ----
        if (cta < 64) {
            float2 rv = sgemm3(g_difft, 64, m0, g_W2p[t & 1] + n0, false, sm, tid);
            if (tid < 256) {
                float2 hp = *(const float2*)&g_h[(size_t)(64 + m)*DD + n];
                *(float2*)&g_dpre[(size_t)m*DD + n] =
                    make_float2(hp.x > 0.f ? rv.x : 0.f, hp.y > 0.f ? rv.y : 0.f);
            }
        } else {
            float th = g_th[t], et = g_et[t], al = g_al[t];
            float ls = g_loss[t] * (1.f/(float)NBD);
            float pt = (ls >= 1e-10f && ls <= 1e10f) ? 1.f : 0.f;
            float s  = th * pt * (2.f/(float)NBD);
            float oa = 1.f - al;
            const float* W2old = g_W2p[t & 1];
            float* W2new = g_W2p[(t + 1) & 1];
            int id = cta - 64;
            int i0 = (id >> 2) * 32, j0 = (id & 3) * 128;
            float (*Ag)[36]  = (float(*)[36])sm;
            float (*Bg)[132] = (float(*)[132])(sm + 64*36);
            { int e = tid; int b = e >> 3, iq = e & 7;
              *(float4*)&Ag[b][iq*4] = *(const float4*)&g_diff[(size_t)b*DD + i0 + iq*4]; }
            #pragma unroll
            for (int i = 0; i < 4; i++) {
                int e = tid + i*512; int b = e >> 5, jq = e & 31;
                float4 v = *(const float4*)&g_h[(size_t)(64 + b)*DD + j0 + jq*4];
                v.x=fmaxf(v.x,0.f); v.y=fmaxf(v.y,0.f); v.z=fmaxf(v.z,0.f); v.w=fmaxf(v.w,0.f);
                *(float4*)&Bg[b][jq*4] = v;
            }
            __syncthreads();
            int ti = tid >> 5, tj = tid & 31;
            u64 q00=0ull, q01=0ull, q10=0ull, q11=0ull;
            #pragma unroll 8
            for (int b = 0; b < 64; b++) {
                float2 av = *(const float2*)&Ag[b][ti*2];
                ulonglong2 bv = *(const ulonglong2*)&Bg[b][tj*4];
                u64 s0 = pk2(av.x,av.x), s1 = pk2(av.y,av.y);
                fma2(q00,s0,bv.x); fma2(q01,s0,bv.y);
                fma2(q10,s1,bv.x); fma2(q11,s1,bv.y);
            }
            float gr[2][4];
            { float2 p;
              p=up2(q00); gr[0][0]=p.x; gr[0][1]=p.y; p=up2(q01); gr[0][2]=p.x; gr[0][3]=p.y;
              p=up2(q10); gr[1][0]=p.x; gr[1][1]=p.y; p=up2(q11); gr[1][2]=p.x; gr[1][3]=p.y; }
            #pragma unroll
            for (int h = 0; h < 2; h++) {
                int iw = i0 + ti*2 + h, jw = j0 + tj*4;
                size_t idx = (size_t)iw*DD + jw;
                float4 mm = *(const float4*)&g_M2w[idx];
                float4 wo = *(const float4*)&W2old[idx];
                mm.x = et*mm.x - s*gr[h][0]; wo.x = oa*wo.x + mm.x;
                mm.y = et*mm.y - s*gr[h][1]; wo.y = oa*wo.y + mm.y;
                mm.z = et*mm.z - s*gr[h][2]; wo.z = oa*wo.z + mm.z;
                mm.w = et*mm.w - s*gr[h][3]; wo.w = oa*wo.w + mm.w;
                *(float4*)&g_M2w[idx] = mm; *(float4*)&W2new[idx] = wo;
                g_W2t[(size_t)(jw+0)*DD + iw] = wo.x; g_W2t[(size_t)(jw+1)*DD + iw] = wo.y;
                g_W2t[(size_t)(jw+2)*DD + iw] = wo.z; g_W2t[(size_t)(jw+3)*DD + iw] = wo.w;
            }
            if ((id & 3) == 0 && tid < 32) {
                int c = i0 + tid; float g = 0.f;
                #pragma unroll 8
                for (int b = 0; b < 64; b++) g += Ag[b][tid];
                float m2 = et*g_M2b[c] - s*g; g_M2b[c] = m2; g_b2[c] = oa*g_b2[c] + m2;
            }
        }
        gbar(gen);
    }
}

extern "C" void kernel_launch(void* const* d_in, const int* in_sizes, int n_in,
                              void* d_out, int out_size) {
    const float* x   = (const float*)d_in[0];
    const float* WQ  = (const float*)d_in[1];
    const float* WK  = (const float*)d_in[2];
    const float* WV  = (const float*)d_in[3];
    const float* thw = (const float*)d_in[4];
    const float* thb = (const float*)d_in[5];
    const float* etw = (const float*)d_in[6];
    const float* etb = (const float*)d_in[7];
    const float* alw = (const float*)d_in[8];
    const float* alb = (const float*)d_in[9];
    const float* W1  = (const float*)d_in[10];
    const float* b1  = (const float*)d_in[11];
    const float* W2  = (const float*)d_in[12];
    const float* b2  = (const float*)d_in[13];
    float* out = (float*)d_out;
    int dup = (out_size >= 2 * BTD) ? 1 : 0;

    cudaFuncSetAttribute(k_scan, cudaFuncAttributeMaxDynamicSharedMemorySize, SCAN_SMEM);
    k_init<<<1024, 256>>>(W1, b1, W2, b2);
    k_gates<<<TT, 256>>>(x, thw, thb, etw, etb, alw, alb);
    k_qkv<<<dim3(8, 128, 3), 256>>>(x, WQ, WK, WV);
    k_scan<<<G_CTAS, 512, SCAN_SMEM>>>(out, dup);
}

// round 11
// speedup vs baseline: 2.0601x; 1.1578x over previous
#include <cuda_runtime.h>
#include <math.h>

#define BB 64
#define TT 128
#define DD 512
#define NBD (BB*DD)
#define BTD (BB*TT*DD)
#define G_CTAS 128
#define SCAN_SMEM 106496

typedef unsigned long long u64;

__device__ float g_Qt[TT*NBD];     // [t][k][b]
__device__ float g_Kt[TT*NBD];     // [t][k][b]
__device__ float g_K [TT*NBD];     // [t][b][k]
__device__ float g_V [TT*NBD];     // [t][b][k]
__device__ float g_th[TT], g_et[TT], g_al[TT];
__device__ float g_W1[DD*DD], g_M1w[DD*DD], g_b1[DD], g_M1b[DD];
__device__ float g_W2p[2][DD*DD];  // ping-pong row-major W2 (read parity t&1)
__device__ float g_M2w[DD*DD], g_b2[DD], g_M2b[DD];
__device__ float g_W1t[DD*DD], g_W2t[DD*DD];   // [k][n]
__device__ float g_h[2*NBD];
__device__ float g_ht[2*NBD];      // [n][m]
__device__ float g_diff[NBD];      // [b][n]
__device__ float g_difft[NBD];     // [n][b]
__device__ float g_dpre[NBD];      // [b][n]
__device__ float g_loss[TT];
__device__ unsigned g_barcnt[32][32];   // padded counters: use [c][0]

__device__ __forceinline__ u64 pk2(float x, float y){
    u64 r; asm("mov.b64 %0, {%1, %2};" : "=l"(r) : "f"(x), "f"(y)); return r;
}
__device__ __forceinline__ void fma2(u64 &c, u64 a, u64 b){
    asm("fma.rn.f32x2 %0, %1, %2, %0;" : "+l"(c) : "l"(a), "l"(b));
}
__device__ __forceinline__ u64 add2(u64 a, u64 b){
    u64 r; asm("add.rn.f32x2 %0, %1, %2;" : "=l"(r) : "l"(a), "l"(b)); return r;
}
__device__ __forceinline__ float2 up2(u64 v){
    float lo, hi; asm("mov.b64 {%0, %1}, %2;" : "=f"(lo), "=f"(hi) : "l"(v));
    return make_float2(lo, hi);
}
__device__ __forceinline__ unsigned smaddr(const void* p){
    return (unsigned)__cvta_generic_to_shared(p);
}

// Distributed grid barrier: 32 counters (4 CTAs each), warp-parallel acquire poll.
__device__ __forceinline__ void gbar(unsigned &gen){
    __syncthreads();
    if (threadIdx.x < 32){
        if (threadIdx.x == 0){
            unsigned d;
            asm volatile("atom.acq_rel.gpu.global.add.u32 %0, [%1], 1;"
                         : "=r"(d) : "l"(&g_barcnt[blockIdx.x & 31][0]) : "memory");
        }
        unsigned target = (gen + 1u) * 4u;
        unsigned v;
        do {
            asm volatile("ld.acquire.gpu.global.u32 %0, [%1];"
                         : "=r"(v) : "l"(&g_barcnt[threadIdx.x][0]) : "memory");
        } while (__any_sync(0xffffffffu, v < target));
    }
    __syncthreads();
    gen++;
}

__global__ void k_init(const float* __restrict__ W1, const float* __restrict__ b1,
                       const float* __restrict__ W2, const float* __restrict__ b2) {
    int i = blockIdx.x * 256 + threadIdx.x;
    if (i < DD*DD) {
        g_W1[i] = W1[i]; g_M1w[i] = 0.f; g_W2p[0][i] = W2[i]; g_M2w[i] = 0.f;
        int tr = (i & 511) * 512 + (i >> 9);
        g_W1t[tr] = W1[i]; g_W2t[tr] = W2[i];
    }
    if (i < DD) { g_b1[i] = b1[i]; g_M1b[i] = 0.f; g_b2[i] = b2[i]; g_M2b[i] = 0.f; }
    if (i < TT) g_loss[i] = 0.f;
    if (i < 1024) ((unsigned*)g_barcnt)[i] = 0u;
}

__global__ void k_gates(const float* __restrict__ x,
                        const float* __restrict__ thw, const float* __restrict__ thb,
                        const float* __restrict__ etw, const float* __restrict__ etb,
                        const float* __restrict__ alw, const float* __restrict__ alb) {
    int t = blockIdx.x, tid = threadIdx.x, lane = tid & 31, warp = tid >> 5;
    __shared__ float red[8];
    for (int g = 0; g < 3; g++) {
        const float* w = (g == 0) ? thw : ((g == 1) ? etw : alw);
        float b0 = (g == 0) ? thb[0] : ((g == 1) ? etb[0] : alb[0]);
        float acc = 0.f;
        for (int bi = warp; bi < BB; bi += 8) {
            const float* xr = x + ((size_t)bi * TT + t) * DD;
            float s = 0.f;
            for (int k = lane; k < DD; k += 32) s += xr[k] * w[k];
            #pragma unroll
            for (int o = 16; o; o >>= 1) s += __shfl_down_sync(0xffffffffu, s, o);
            if (lane == 0) acc += 1.f / (1.f + expf(-(s + b0)));
        }
        if (lane == 0) red[warp] = acc;
        __syncthreads();
        if (tid == 0) {
            float s = 0.f;
            #pragma unroll
            for (int i = 0; i < 8; i++) s += red[i];
            s *= (1.f / (float)BB);
            if (g == 0) g_th[t] = s; else if (g == 1) g_et[t] = s; else g_al[t] = s;
        }
        __syncthreads();
    }
}

__global__ __launch_bounds__(256) void k_qkv(const float* __restrict__ x,
                       const float* __restrict__ WQ, const float* __restrict__ WK,
                       const float* __restrict__ WV) {
    __shared__ __align__(16) float qsm[4352];
    float (*As)[33]  = (float(*)[33])qsm;           // 64x33
    float (*Bsk)[68] = (float(*)[68])(qsm + 2112);  // 32x68
    int n0 = blockIdx.x * 64, m0 = blockIdx.y * 64, z = blockIdx.z;
    const float* W = (z == 0) ? WQ : ((z == 1) ? WK : WV);
    int tid = threadIdx.x;
    int r0 = (tid >> 4) * 4, c0 = (tid & 15) * 4;
    u64 acc[4][2];
    #pragma unroll
    for (int i = 0; i < 4; i++) { acc[i][0] = 0ull; acc[i][1] = 0ull; }
    for (int kb = 0; kb < 16; kb++) {
        #pragma unroll
        for (int i = 0; i < 2; i++) {
            int e = tid + i*256; int row = e >> 3, kq = e & 7;
            int m = m0 + row;
            float4 xv = *(const float4*)&x[((size_t)(m & 63)*TT + (m >> 6))*DD + kb*32 + kq*4];
            As[row][4*kq+0]=xv.x; As[row][4*kq+1]=xv.y; As[row][4*kq+2]=xv.z; As[row][4*kq+3]=xv.w;
            float4 wv = *(const float4*)&W[(size_t)(n0 + row)*DD + kb*32 + kq*4];
            Bsk[4*kq+0][row]=wv.x; Bsk[4*kq+1][row]=wv.y; Bsk[4*kq+2][row]=wv.z; Bsk[4*kq+3][row]=wv.w;
        }
        __syncthreads();
        #pragma unroll 8
        for (int kk = 0; kk < 32; kk++) {
            float a0 = As[r0+0][kk], a1 = As[r0+1][kk], a2 = As[r0+2][kk], a3 = As[r0+3][kk];
            ulonglong2 bb = *(const ulonglong2*)&Bsk[kk][c0];
            u64 sx;
            sx = pk2(a0,a0); fma2(acc[0][0],sx,bb.x); fma2(acc[0][1],sx,bb.y);
            sx = pk2(a1,a1); fma2(acc[1][0],sx,bb.x); fma2(acc[1][1],sx,bb.y);
            sx = pk2(a2,a2); fma2(acc[2][0],sx,bb.x); fma2(acc[2][1],sx,bb.y);
            sx = pk2(a3,a3); fma2(acc[3][0],sx,bb.x); fma2(acc[3][1],sx,bb.y);
        }
        __syncthreads();
    }
    float (*T)[68] = (float(*)[68])qsm;   // 64x68 transpose staging (reuses As/Bsk)
    #pragma unroll
    for (int i = 0; i < 4; i++) {
        float2 p0 = up2(acc[i][0]), p1 = up2(acc[i][1]);
        float4 v = make_float4(p0.x, p0.y, p1.x, p1.y);
        if (z == 2) { *(float4*)&g_V[(size_t)(m0+r0+i)*DD + n0 + c0] = v; }
        else {
            if (z == 1) *(float4*)&g_K[(size_t)(m0+r0+i)*DD + n0 + c0] = v;
            T[c0+0][r0+i] = p0.x; T[c0+1][r0+i] = p0.y;
            T[c0+2][r0+i] = p1.x; T[c0+3][r0+i] = p1.y;
        }
    }
    if (z < 2) {
        __syncthreads();
        float* Ot = ((z == 0) ? g_Qt : g_Kt) + (size_t)(m0 >> 6)*NBD;
        #pragma unroll
        for (int i = 0; i < 4; i++) {
            int e = tid + i*256;                 // 0..1023
            int nl = e >> 4, b4 = (e & 15) * 4;
            *(float4*)&Ot[(size_t)(n0 + nl)*64 + b4] = *(float4*)&T[nl][b4];
        }
    }
}

// C[8x64] = A(k-major [512][Ms], rows moff..+8) @ Bk(k-major rows, stride DD)
// 512 threads, split-K x8, cp.async double-buffered B. Result for tid<256.
__device__ __forceinline__ float2 sgemm3(const float* __restrict__ Akt, int Ms, int moff,
                                         const float* __restrict__ Bk, bool reluA,
                                         float* sm, int tid) {
    float* At   = sm;            // 4096
    float* Bs   = sm + 4096;     // 2 x [128][68]
    float* sred = sm + 21504;    // 512*10
    #pragma unroll
    for (int c = 0; c < 2; c++) {
        #pragma unroll
        for (int i = 0; i < 4; i++) {
            int e = tid + i*512; int kq = e >> 4, nq = e & 15;
            unsigned dst = smaddr(&Bs[c*8704 + kq*68 + nq*4]);
            const float* src = &Bk[(size_t)(c*128 + kq)*DD + nq*4];
            asm volatile("cp.async.ca.shared.global [%0], [%1], 16;" :: "r"(dst), "l"(src));
        }
        asm volatile("cp.async.commit_group;");
    }
    #pragma unroll
    for (int i = 0; i < 2; i++) {
        int e = tid + i*512; int k = e >> 1, mq = (e & 1)*4;
        float4 v = *(const float4*)&Akt[(size_t)k*Ms + moff + mq];
        if (reluA) { v.x=fmaxf(v.x,0.f); v.y=fmaxf(v.y,0.f); v.z=fmaxf(v.z,0.f); v.w=fmaxf(v.w,0.f); }
        *(float4*)&At[k*8 + mq] = v;
    }
    int ks = tid >> 6, rq = (tid >> 5) & 1, cv = tid & 31;
    u64 ac0=0ull, ac1=0ull, ac2=0ull, ac3=0ull;
    for (int c = 0; c < 4; c++) {
        asm volatile("cp.async.wait_group 1;");
        __syncthreads();
        const float* ap = At + (c*128 + ks*16)*8 + rq*4;
        const float* bp = Bs + (c&1)*8704 + (ks*16)*68 + 2*cv;
        #pragma unroll
        for (int kk = 0; kk < 16; kk++) {
            float4 a = *(const float4*)(ap + kk*8);
            u64 b = *(const u64*)(bp + kk*68);
            fma2(ac0, pk2(a.x,a.x), b);
            fma2(ac1, pk2(a.y,a.y), b);
            fma2(ac2, pk2(a.z,a.z), b);
            fma2(ac3, pk2(a.w,a.w), b);
        }
        __syncthreads();
        if (c < 2) {
            #pragma unroll
            for (int i = 0; i < 4; i++) {
                int e = tid + i*512; int kq = e >> 4, nq = e & 15;
                unsigned dst = smaddr(&Bs[(c&1)*8704 + kq*68 + nq*4]);
                const float* src = &Bk[(size_t)((c+2)*128 + kq)*DD + nq*4];
                asm volatile("cp.async.ca.shared.global [%0], [%1], 16;" :: "r"(dst), "l"(src));
            }
        }
        asm volatile("cp.async.commit_group;");
    }
    u64* rp = (u64*)&sred[tid*10];
    rp[0]=ac0; rp[1]=ac1; rp[2]=ac2; rp[3]=ac3;
    __syncthreads();
    float2 T = make_float2(0.f, 0.f);
    if (tid < 256) {
        int m = tid >> 5, c2 = tid & 31, rq2 = m >> 2, ri = m & 3;
        u64 acc = 0ull;
        #pragma unroll
        for (int k2 = 0; k2 < 8; k2++)
            acc = add2(acc, *(const u64*)&sred[((k2*2 + rq2)*32 + c2)*10 + ri*2]);
        T = up2(acc);
    }
    return T;
}

__global__ __launch_bounds__(512, 1) void k_scan(float* __restrict__ out, int dup) {
    extern __shared__ __align__(16) float sm[];
    __shared__ float red[16];
    int cta = blockIdx.x, tid = threadIdx.x;
    unsigned gen = 0;

    for (int t = 0; t < TT; t++) {
        // ---- U: gW1 + W1/b1 update (grads of t-1) ----
        if (t > 0) {
            float th = g_th[t-1], et = g_et[t-1], al = g_al[t-1];
            float ls = g_loss[t-1] * (1.f/(float)NBD);
            float pt = (ls >= 1e-10f && ls <= 1e10f) ? 1.f : 0.f;
            float s  = th * pt * (2.f/(float)NBD);
            float oa = 1.f - al;
            int i0 = (cta >> 3) * 32, j0 = (cta & 7) * 64;
            float (*sDp)[36] = (float(*)[36])sm;               // 64x36
            float (*sK)[68]  = (float(*)[68])(sm + 2304);      // 64x68
            float (*wT)[36]  = (float(*)[36])(sm + 6656);      // 64x36
            { int e = tid; int b = e >> 3, iq = e & 7;
              *(float4*)&sDp[b][iq*4] = *(const float4*)&g_dpre[(size_t)b*DD + i0 + iq*4]; }
            const float* Kt = g_K + (size_t)(t-1)*NBD;
            #pragma unroll
            for (int i = 0; i < 2; i++) {
                int e = tid + i*512; int b = e >> 4, jq = e & 15;
                *(float4*)&sK[b][jq*4] = *(const float4*)&Kt[(size_t)b*DD + j0 + jq*4];
            }
            __syncthreads();
            int ti = tid >> 4, tj = tid & 15;
            u64 a0 = 0ull, a1 = 0ull;
            #pragma unroll 8
            for (int b = 0; b < 64; b++) {
                float av = sDp[b][ti];
                ulonglong2 bv = *(const ulonglong2*)&sK[b][tj*4];
                u64 sx = pk2(av, av);
                fma2(a0, sx, bv.x); fma2(a1, sx, bv.y);
            }
            float2 p0 = up2(a0), p1 = up2(a1);
            int iw = i0 + ti, jw = j0 + tj*4;
            size_t idx = (size_t)iw*DD + jw;
            float4 mm = *(const float4*)&g_M1w[idx];
            float4 ww = *(const float4*)&g_W1[idx];
            mm.x = et*mm.x - s*p0.x; ww.x = oa*ww.x + mm.x;
            mm.y = et*mm.y - s*p0.y; ww.y = oa*ww.y + mm.y;
            mm.z = et*mm.z - s*p1.x; ww.z = oa*ww.z + mm.z;
            mm.w = et*mm.w - s*p1.y; ww.w = oa*ww.w + mm.w;
            *(float4*)&g_M1w[idx] = mm; *(float4*)&g_W1[idx] = ww;
            wT[tj*4+0][ti] = ww.x; wT[tj*4+1][ti] = ww.y;
            wT[tj*4+2][ti] = ww.z; wT[tj*4+3][ti] = ww.w;
            if ((cta & 7) == 0 && tid < 32) {
                int c = i0 + tid; float g = 0.f;
                #pragma unroll 8
                for (int b = 0; b < 64; b++) g += sDp[b][tid];
                float m = et*g_M1b[c] - s*g; g_M1b[c] = m; g_b1[c] = oa*g_b1[c] + m;
            }
            __syncthreads();
            { int jl = tid >> 3, i4 = (tid & 7) * 4;
              *(float4*)&g_W1t[(size_t)(j0+jl)*DD + i0 + i4] = *(float4*)&wT[jl][i4]; }
            gbar(gen);
        }

        int m0 = (cta >> 3) * 8, n0 = (cta & 7) * 64;
        int r = tid >> 5, c2 = (tid & 31) * 2;
        int m = m0 + r, n = n0 + c2;

        // ---- H ----
        {
            const float* Akt = (m0 < 64) ? (g_Qt + (size_t)t*NBD) : (g_Kt + (size_t)t*NBD);
            int moff = (m0 < 64) ? m0 : (m0 - 64);
            float2 rv = sgemm3(Akt, 64, moff, g_W1t + n0, false, sm, tid);
            float (*hT)[9] = (float(*)[9])sm;
            if (tid < 256) {
                rv.x += g_b1[n]; rv.y += g_b1[n+1];
                *(float2*)&g_h[(size_t)m*DD + n] = rv;
                hT[c2][r] = rv.x; hT[c2+1][r] = rv.y;
            }
            __syncthreads();
            if (tid < 128) {
                int nl = tid >> 1, m4 = (tid & 1) * 4;
                float4 v = make_float4(hT[nl][m4], hT[nl][m4+1], hT[nl][m4+2], hT[nl][m4+3]);
                *(float4*)&g_ht[(size_t)(n0+nl)*128 + m0 + m4] = v;
            }
        }
        gbar(gen);

        // ---- O ----
        {
            float2 rv = sgemm3(g_ht, 128, m0, g_W2t + n0, true, sm, tid);
            float (*dT)[9] = (float(*)[9])sm;
            float lsv = 0.f;
            if (tid < 256) {
                rv.x += g_b2[n]; rv.y += g_b2[n+1];
                if (m0 < 64) {
                    size_t o = ((size_t)m*TT + t)*DD + n;
                    *(float2*)&out[o] = rv;
                    if (dup) *(float2*)&out[BTD + o] = rv;
                } else {
                    int b = m - 64;
                    float2 v = *(const float2*)&g_V[(size_t)t*NBD + (size_t)b*DD + n];
                    float d0 = rv.x - v.x, d1 = rv.y - v.y;
                    *(float2*)&g_diff[(size_t)b*DD + n] = make_float2(d0, d1);
                    dT[c2][r] = d0; dT[c2+1][r] = d1;
                    lsv = d0*d0 + d1*d1;
                }
            }
            if (m0 >= 64) {
                #pragma unroll
                for (int o2 = 16; o2; o2 >>= 1) lsv += __shfl_down_sync(0xffffffffu, lsv, o2);
                if ((tid & 31) == 0) red[tid >> 5] = lsv;
                __syncthreads();
                if (tid == 0) {
                    float sv = 0.f;
                    #pragma unroll
                    for (int i = 0; i < 16; i++) sv += red[i];
                    atomicAdd(&g_loss[t], sv);
                }
                if (tid < 128) {
                    int nl = tid >> 1, b4 = (tid & 1) * 4;
                    float4 v = make_float4(dT[nl][b4], dT[nl][b4+1], dT[nl][b4+2], dT[nl][b4+3]);
                    *(float4*)&g_difft[(size_t)(n0+nl)*64 + (m0 - 64) + b4] = v;
                }
            }
        }
        if (t == TT-1) break;
        gbar(gen);

        // ---- D: CTAs 0-63 dpre ; CTAs 64-127 gW2 + fused W2/b2 update ----
        if (cta < 64) {
            float2 rv = sgemm3(g_difft, 64, m0, g_W2p[t & 1] + n0, false, sm, tid);
            if (tid < 256) {
                float2 hp = *(const float2*)&g_h[(size_t)(64 + m)*DD + n];
                *(float2*)&g_dpre[(size_t)m*DD + n] =
                    make_float2(hp.x > 0.f ? rv.x : 0.f, hp.y > 0.f ? rv.y : 0.f);
            }
        } else {
            float th = g_th[t], et = g_et[t], al = g_al[t];
            float ls = g_loss[t] * (1.f/(float)NBD);
            float pt = (ls >= 1e-10f && ls <= 1e10f) ? 1.f : 0.f;
            float s  = th * pt * (2.f/(float)NBD);
            float oa = 1.f - al;
            const float* W2old = g_W2p[t & 1];
            float* W2new = g_W2p[(t + 1) & 1];
            int id = cta - 64;
            int i0 = (id >> 2) * 32, j0 = (id & 3) * 128;
            float (*Ag)[36]  = (float(*)[36])sm;               // 64x36
            float (*Bg)[132] = (float(*)[132])(sm + 2304);     // 64x132
            float (*wT)[36]  = (float(*)[36])(sm + 10752);     // 128x36
            { int e = tid; int b = e >> 3, iq = e & 7;
              *(float4*)&Ag[b][iq*4] = *(const float4*)&g_diff[(size_t)b*DD + i0 + iq*4]; }
            #pragma unroll
            for (int i = 0; i < 4; i++) {
                int e = tid + i*512; int b = e >> 5, jq = e & 31;
                float4 v = *(const float4*)&g_h[(size_t)(64 + b)*DD + j0 + jq*4];
                v.x=fmaxf(v.x,0.f); v.y=fmaxf(v.y,0.f); v.z=fmaxf(v.z,0.f); v.w=fmaxf(v.w,0.f);
                *(float4*)&Bg[b][jq*4] = v;
            }
            __syncthreads();
            int ti = tid >> 5, tj = tid & 31;
            u64 q00=0ull, q01=0ull, q10=0ull, q11=0ull;
            #pragma unroll 8
            for (int b = 0; b < 64; b++) {
                float2 av = *(const float2*)&Ag[b][ti*2];
                ulonglong2 bv = *(const ulonglong2*)&Bg[b][tj*4];
                u64 s0 = pk2(av.x,av.x), s1 = pk2(av.y,av.y);
                fma2(q00,s0,bv.x); fma2(q01,s0,bv.y);
                fma2(q10,s1,bv.x); fma2(q11,s1,bv.y);
            }
            float gr[2][4];
            { float2 p;
              p=up2(q00); gr[0][0]=p.x; gr[0][1]=p.y; p=up2(q01); gr[0][2]=p.x; gr[0][3]=p.y;
              p=up2(q10); gr[1][0]=p.x; gr[1][1]=p.y; p=up2(q11); gr[1][2]=p.x; gr[1][3]=p.y; }
            #pragma unroll
            for (int h = 0; h < 2; h++) {
                int iw = i0 + ti*2 + h, jw = j0 + tj*4;
                size_t idx = (size_t)iw*DD + jw;
                float4 mm = *(const float4*)&g_M2w[idx];
                float4 wo = *(const float4*)&W2old[idx];
                mm.x = et*mm.x - s*gr[h][0]; wo.x = oa*wo.x + mm.x;
                mm.y = et*mm.y - s*gr[h][1]; wo.y = oa*wo.y + mm.y;
                mm.z = et*mm.z - s*gr[h][2]; wo.z = oa*wo.z + mm.z;
                mm.w = et*mm.w - s*gr[h][3]; wo.w = oa*wo.w + mm.w;
                *(float4*)&g_M2w[idx] = mm; *(float4*)&W2new[idx] = wo;
                wT[tj*4+0][ti*2+h] = wo.x; wT[tj*4+1][ti*2+h] = wo.y;
                wT[tj*4+2][ti*2+h] = wo.z; wT[tj*4+3][ti*2+h] = wo.w;
            }
            if ((id & 3) == 0 && tid < 32) {
                int c = i0 + tid; float g = 0.f;
                #pragma unroll 8
                for (int b = 0; b < 64; b++) g += Ag[b][tid];
                float m2 = et*g_M2b[c] - s*g; g_M2b[c] = m2; g_b2[c] = oa*g_b2[c] + m2;
            }
            __syncthreads();
            #pragma unroll
            for (int i2 = 0; i2 < 2; i2++) {
                int e = tid + i2*512;                // 0..1023
                int jl = e >> 3, i4 = (e & 7) * 4;
                *(float4*)&g_W2t[(size_t)(j0+jl)*DD + i0 + i4] = *(float4*)&wT[jl][i4];
            }
        }
        gbar(gen);
    }
}

extern "C" void kernel_launch(void* const* d_in, const int* in_sizes, int n_in,
                              void* d_out, int out_size) {
    const float* x   = (const float*)d_in[0];
    const float* WQ  = (const float*)d_in[1];
    const float* WK  = (const float*)d_in[2];
    const float* WV  = (const float*)d_in[3];
    const float* thw = (const float*)d_in[4];
    const float* thb = (const float*)d_in[5];
    const float* etw = (const float*)d_in[6];
    const float* etb = (const float*)d_in[7];
    const float* alw = (const float*)d_in[8];
    const float* alb = (const float*)d_in[9];
    const float* W1  = (const float*)d_in[10];
    const float* b1  = (const float*)d_in[11];
    const float* W2  = (const float*)d_in[12];
    const float* b2  = (const float*)d_in[13];
    float* out = (float*)d_out;
    int dup = (out_size >= 2 * BTD) ? 1 : 0;

    cudaFuncSetAttribute(k_scan, cudaFuncAttributeMaxDynamicSharedMemorySize, SCAN_SMEM);
    k_init<<<1024, 256>>>(W1, b1, W2, b2);
    k_gates<<<TT, 256>>>(x, thw, thb, etw, etb, alw, alb);
    k_qkv<<<dim3(8, 128, 3), 256>>>(x, WQ, WK, WV);
    k_scan<<<G_CTAS, 512, SCAN_SMEM>>>(out, dup);
}